// round 2
// baseline (speedup 1.0000x reference)
#include <cuda_runtime.h>

#define N_NODES  200000
#define N_EDGES  1600000
#define N_GRAPHS 10000
#define IN_F     74
#define HID      128

// ---------------- scratch (device globals; no allocation allowed) ----------------
__device__ __align__(16) float g_h  [(size_t)N_NODES * HID];
__device__ __align__(16) float g_agg[(size_t)N_NODES * HID];
__device__ __align__(16) int   g_deg_out[N_NODES];
__device__ __align__(16) int   g_deg_in [N_NODES];
__device__ __align__(16) float g_norm_src[N_NODES];
__device__ __align__(16) float g_norm_dst[N_NODES];
__device__ __align__(16) float g_pooled[(size_t)N_GRAPHS * HID];

// ---------------- utility kernels ----------------
__global__ void zero4_kernel(float4* p, int n4) {
    int i = blockIdx.x * blockDim.x + threadIdx.x;
    if (i < n4) p[i] = make_float4(0.f, 0.f, 0.f, 0.f);
}

__global__ void degree_kernel(const int* __restrict__ src, const int* __restrict__ dst) {
    int i = blockIdx.x * blockDim.x + threadIdx.x;
    if (i < N_EDGES) {
        atomicAdd(&g_deg_out[src[i]], 1);
        atomicAdd(&g_deg_in [dst[i]], 1);
    }
}

__global__ void norm_kernel() {
    int i = blockIdx.x * blockDim.x + threadIdx.x;
    if (i < N_NODES) {
        g_norm_src[i] = rsqrtf(fmaxf((float)g_deg_out[i], 1.f));
        g_norm_dst[i] = rsqrtf(fmaxf((float)g_deg_in [i], 1.f));
    }
}

// SpMM scatter: one warp per edge. g_h rows are already scaled by norm_src.
// agg[dst] += h[src]  via vector reduction (red.global.add.v4.f32, sm_90+).
__global__ void scatter_kernel(const int* __restrict__ src, const int* __restrict__ dst) {
    int e    = (blockIdx.x * blockDim.x + threadIdx.x) >> 5;
    int lane = threadIdx.x & 31;
    if (e >= N_EDGES) return;
    int s = __ldg(src + e);
    int d = __ldg(dst + e);
    const float4 v = *reinterpret_cast<const float4*>(g_h + (size_t)s * HID + lane * 4);
    float* p = g_agg + (size_t)d * HID + lane * 4;
    asm volatile("red.global.add.v4.f32 [%0], {%1,%2,%3,%4};"
                 :: "l"(p), "f"(v.x), "f"(v.y), "f"(v.z), "f"(v.w) : "memory");
}

// ---------------- GEMM: C[M,128] = epilogue( A[M,K] @ B[K,128] ) ----------------
// Block: 128 rows x 128 cols. 256 threads, 8x8 per thread, packed f32x2 FFMA.
// Epilogue: v = acc*in_scale[row] + bias[col]; optional SiLU; v *= out_scale[row];
// then either store to C or atomically pool into g_pooled[gids[row]].
__global__ __launch_bounds__(256)
void gemm_kernel(const float* __restrict__ A, int M, int K, int lda,
                 const float* __restrict__ B,          // [K][128] row-major
                 const float* __restrict__ bias,       // [128]
                 const float* __restrict__ in_scale,   // per-row or null
                 const float* __restrict__ out_scale,  // per-row or null
                 int apply_silu,
                 float* __restrict__ C,                // used if gids == null
                 const int* __restrict__ gids)         // pool mode if non-null
{
    __shared__ unsigned long long As2[8][128];  // A value duplicated into both halves
    __shared__ float              Bs [8][128];

    const int t    = threadIdx.x;
    const int tx   = t & 15;        // col group 0..15
    const int ty   = t >> 4;        // row group 0..15
    const int row0 = blockIdx.x * 128;

    const int arow = t >> 1;        // 0..127
    const int akl  = (t & 1) * 4;   // 0 or 4
    const int brow = t >> 5;        // 0..7
    const int bcol = (t & 31) * 4;  // 0..124

    unsigned long long acc[8][4];
#pragma unroll
    for (int i = 0; i < 8; i++)
#pragma unroll
        for (int j = 0; j < 4; j++) acc[i][j] = 0ULL;

    for (int k0 = 0; k0 < K; k0 += 8) {
        // --- load A tile (scalar loads: handles lda=74 misalignment + K tails) ---
        {
            int gr = row0 + arow;
#pragma unroll
            for (int i = 0; i < 4; i++) {
                int kk = k0 + akl + i;
                float a = 0.f;
                if (gr < M && kk < K) a = __ldg(A + (size_t)gr * lda + kk);
                unsigned long long pk;
                asm("mov.b64 %0, {%1, %1};" : "=l"(pk) : "f"(a));
                As2[akl + i][arow] = pk;
            }
        }
        // --- load B tile ---
        {
            int kk = k0 + brow;
            float4 b = make_float4(0.f, 0.f, 0.f, 0.f);
            if (kk < K) b = *reinterpret_cast<const float4*>(B + (size_t)kk * 128 + bcol);
            *reinterpret_cast<float4*>(&Bs[brow][bcol]) = b;
        }
        __syncthreads();

#pragma unroll
        for (int k = 0; k < 8; k++) {
            // cols: tx*4..tx*4+3  and  64+tx*4..64+tx*4+3  (conflict-free LDS.128)
            ulonglong2 u0 = *reinterpret_cast<const ulonglong2*>(&Bs[k][tx * 4]);
            ulonglong2 u1 = *reinterpret_cast<const ulonglong2*>(&Bs[k][64 + tx * 4]);
            unsigned long long bp[4] = {u0.x, u0.y, u1.x, u1.y};
#pragma unroll
            for (int i = 0; i < 8; i++) {
                unsigned long long a2 = As2[k][ty * 8 + i];
#pragma unroll
                for (int j = 0; j < 4; j++)
                    asm("fma.rn.f32x2 %0, %1, %2, %0;"
                        : "+l"(acc[i][j]) : "l"(a2), "l"(bp[j]));
            }
        }
        __syncthreads();
    }

    // --- epilogue ---
    float4 bb0 = *reinterpret_cast<const float4*>(bias + tx * 4);
    float4 bb1 = *reinterpret_cast<const float4*>(bias + 64 + tx * 4);
    float bia[8] = {bb0.x, bb0.y, bb0.z, bb0.w, bb1.x, bb1.y, bb1.z, bb1.w};

#pragma unroll
    for (int i = 0; i < 8; i++) {
        int gr = row0 + ty * 8 + i;
        if (gr >= M) break;
        float is = in_scale  ? __ldg(in_scale  + gr) : 1.f;
        float os = out_scale ? __ldg(out_scale + gr) : 1.f;
        float v[8];
#pragma unroll
        for (int j = 0; j < 4; j++) {
            float lo, hi;
            asm("mov.b64 {%0, %1}, %2;" : "=f"(lo), "=f"(hi) : "l"(acc[i][j]));
            v[2 * j]     = lo;
            v[2 * j + 1] = hi;
        }
#pragma unroll
        for (int j = 0; j < 8; j++) {
            float w = v[j] * is + bia[j];
            if (apply_silu) w = w * (1.f / (1.f + __expf(-w)));
            v[j] = w * os;
        }
        if (gids) {
            int g = __ldg(gids + gr);
            float* p0 = g_pooled + (size_t)g * 128 + tx * 4;
            float* p1 = p0 + 64;
            asm volatile("red.global.add.v4.f32 [%0], {%1,%2,%3,%4};"
                         :: "l"(p0), "f"(v[0]), "f"(v[1]), "f"(v[2]), "f"(v[3]) : "memory");
            asm volatile("red.global.add.v4.f32 [%0], {%1,%2,%3,%4};"
                         :: "l"(p1), "f"(v[4]), "f"(v[5]), "f"(v[6]), "f"(v[7]) : "memory");
        } else {
            *reinterpret_cast<float4*>(C + (size_t)gr * 128 + tx * 4) =
                make_float4(v[0], v[1], v[2], v[3]);
            *reinterpret_cast<float4*>(C + (size_t)gr * 128 + 64 + tx * 4) =
                make_float4(v[4], v[5], v[6], v[7]);
        }
    }
}

// ---------------- launch ----------------
extern "C" void kernel_launch(void* const* d_in, const int* in_sizes, int n_in,
                              void* d_out, int out_size) {
    const float* x     = (const float*)d_in[0];
    const int*   src   = (const int*)  d_in[1];
    const int*   dst   = (const int*)  d_in[2];
    const int*   gid   = (const int*)  d_in[3];
    const float* w_in  = (const float*)d_in[4];
    const float* b_in  = (const float*)d_in[5];
    const float* gw    = (const float*)d_in[6];
    const float* gb    = (const float*)d_in[7];
    const float* w_out = (const float*)d_in[8];
    const float* b_out = (const float*)d_in[9];
    const float* w_ff  = (const float*)d_in[10];
    const float* b_ff  = (const float*)d_in[11];
    float* out = (float*)d_out;

    float *h, *agg, *pooled, *nsrc, *ndst;
    int *dgo, *dgi;
    cudaGetSymbolAddress((void**)&h,      g_h);
    cudaGetSymbolAddress((void**)&agg,    g_agg);
    cudaGetSymbolAddress((void**)&pooled, g_pooled);
    cudaGetSymbolAddress((void**)&nsrc,   g_norm_src);
    cudaGetSymbolAddress((void**)&ndst,   g_norm_dst);
    cudaGetSymbolAddress((void**)&dgo,    g_deg_out);
    cudaGetSymbolAddress((void**)&dgi,    g_deg_in);

    const int ZT = 256;
    // zero degree counters + pooled accumulator
    zero4_kernel<<<(N_NODES / 4 + ZT - 1) / ZT, ZT>>>((float4*)dgo, N_NODES / 4);
    zero4_kernel<<<(N_NODES / 4 + ZT - 1) / ZT, ZT>>>((float4*)dgi, N_NODES / 4);
    zero4_kernel<<<(N_GRAPHS * HID / 4 + ZT - 1) / ZT, ZT>>>((float4*)pooled, N_GRAPHS * HID / 4);

    degree_kernel<<<(N_EDGES + 255) / 256, 256>>>(src, dst);
    norm_kernel<<<(N_NODES + 255) / 256, 256>>>();

    const int rowTiles = (N_NODES + 127) / 128;  // 1563

    // h = silu(x @ w_in + b_in) * norm_src   (pre-scaled for SpMM gather)
    gemm_kernel<<<rowTiles, 256>>>(x, N_NODES, IN_F, IN_F, w_in, b_in,
                                   nullptr, nsrc, 1, h, nullptr);

    for (int l = 0; l < 3; l++) {
        zero4_kernel<<<(N_NODES * HID / 4 + ZT - 1) / ZT, ZT>>>((float4*)agg, N_NODES * HID / 4);
        scatter_kernel<<<(N_EDGES * 32) / 256, 256>>>(src, dst);
        // h = silu( (agg * norm_dst) @ gw[l] + gb[l] ) * (norm_src unless last layer)
        gemm_kernel<<<rowTiles, 256>>>(agg, N_NODES, HID, HID,
                                       gw + (size_t)l * HID * HID, gb + (size_t)l * HID,
                                       ndst, (l < 2) ? nsrc : nullptr, 1, h, nullptr);
    }

    // embedding_out + fused sum-pool: pooled[gid] += silu(h @ w_out + b_out)
    gemm_kernel<<<rowTiles, 256>>>(h, N_NODES, HID, HID, w_out, b_out,
                                   nullptr, nullptr, 1, nullptr, gid);

    // out = pooled @ w_ff + b_ff
    gemm_kernel<<<(N_GRAPHS + 127) / 128, 256>>>(pooled, N_GRAPHS, HID, HID, w_ff, b_ff,
                                                 nullptr, nullptr, 0, out, nullptr);
}

// round 4
// speedup vs baseline: 1.4152x; 1.4152x over previous
#include <cuda_runtime.h>

#define N_NODES  200000
#define N_EDGES  1600000
#define N_GRAPHS 10000
#define IN_F     74
#define HID      128

#define SCAN_B   1024
#define N_SCANB  ((N_NODES + SCAN_B - 1) / SCAN_B)   // 196

// ---------------- scratch (device globals; no allocation allowed) ----------------
__device__ __align__(16) float g_h  [(size_t)N_NODES * HID];
__device__ __align__(16) float g_agg[(size_t)N_NODES * HID];
__device__ __align__(16) int   g_deg_out[N_NODES];
__device__ __align__(16) int   g_deg_in [N_NODES];
__device__ __align__(16) float g_norm_src[N_NODES];
__device__ __align__(16) float g_norm_dst[N_NODES];
__device__ __align__(16) float g_pooled[(size_t)N_GRAPHS * HID];
__device__ __align__(16) int   g_row_ptr[N_NODES + 1];
__device__ __align__(16) int   g_cursor [N_NODES];
__device__ __align__(16) int   g_csr_src[N_EDGES];
__device__ __align__(16) int   g_bsums  [N_SCANB];

// ---------------- utility kernels ----------------
__global__ void zero4_kernel(float4* p, int n4) {
    int i = blockIdx.x * blockDim.x + threadIdx.x;
    if (i < n4) p[i] = make_float4(0.f, 0.f, 0.f, 0.f);
}

__global__ void degree_kernel(const int* __restrict__ src, const int* __restrict__ dst) {
    int i = blockIdx.x * blockDim.x + threadIdx.x;
    if (i < N_EDGES) {
        atomicAdd(&g_deg_out[src[i]], 1);
        atomicAdd(&g_deg_in [dst[i]], 1);
    }
}

__global__ void norm_kernel() {
    int i = blockIdx.x * blockDim.x + threadIdx.x;
    if (i < N_NODES) {
        g_norm_src[i] = rsqrtf(fmaxf((float)g_deg_out[i], 1.f));
        g_norm_dst[i] = rsqrtf(fmaxf((float)g_deg_in [i], 1.f));
    }
}

// ---------------- CSR build: exclusive scan of deg_in -> row_ptr ----------------
__global__ __launch_bounds__(SCAN_B) void scan1_kernel() {
    __shared__ int sh[SCAN_B];
    int i = blockIdx.x * SCAN_B + threadIdx.x;
    int v = (i < N_NODES) ? g_deg_in[i] : 0;
    sh[threadIdx.x] = v;
    __syncthreads();
#pragma unroll
    for (int off = 1; off < SCAN_B; off <<= 1) {
        int t = (threadIdx.x >= off) ? sh[threadIdx.x - off] : 0;
        __syncthreads();
        sh[threadIdx.x] += t;
        __syncthreads();
    }
    if (i < N_NODES) g_row_ptr[i] = sh[threadIdx.x] - v;   // exclusive, local
    if (threadIdx.x == SCAN_B - 1) g_bsums[blockIdx.x] = sh[threadIdx.x];
}

__global__ __launch_bounds__(256) void scan2_kernel() {
    __shared__ int sh[256];
    int v = (threadIdx.x < N_SCANB) ? g_bsums[threadIdx.x] : 0;
    sh[threadIdx.x] = v;
    __syncthreads();
#pragma unroll
    for (int off = 1; off < 256; off <<= 1) {
        int t = (threadIdx.x >= off) ? sh[threadIdx.x - off] : 0;
        __syncthreads();
        sh[threadIdx.x] += t;
        __syncthreads();
    }
    if (threadIdx.x < N_SCANB) g_bsums[threadIdx.x] = sh[threadIdx.x] - v;  // exclusive
}

__global__ void scan3_kernel() {
    int i = blockIdx.x * blockDim.x + threadIdx.x;
    if (i < N_NODES) {
        int rp = g_row_ptr[i] + g_bsums[i / SCAN_B];
        g_row_ptr[i] = rp;
        g_cursor [i] = rp;
    }
    if (i == 0) g_row_ptr[N_NODES] = N_EDGES;
}

__global__ void build_csr_kernel(const int* __restrict__ src, const int* __restrict__ dst) {
    int e = blockIdx.x * blockDim.x + threadIdx.x;
    if (e < N_EDGES) {
        int pos = atomicAdd(&g_cursor[dst[e]], 1);
        g_csr_src[pos] = src[e];
    }
}

// ---------------- SpMM gather: agg[n] = norm_dst[n] * sum_{e in in(n)} h[src_e]
// One warp per node; h rows are pre-scaled by norm_src. No atomics, no zeroing.
__global__ __launch_bounds__(256) void gather_kernel(float* __restrict__ agg) {
    int n    = (blockIdx.x * blockDim.x + threadIdx.x) >> 5;
    int lane = threadIdx.x & 31;
    if (n >= N_NODES) return;
    int e0 = __ldg(&g_row_ptr[n]);
    int e1 = __ldg(&g_row_ptr[n + 1]);
    float4 acc = make_float4(0.f, 0.f, 0.f, 0.f);
    int e = e0;
    for (; e + 2 <= e1; e += 2) {
        int a = __ldg(&g_csr_src[e]);
        int b = __ldg(&g_csr_src[e + 1]);
        float4 va = *reinterpret_cast<const float4*>(g_h + (size_t)a * HID + lane * 4);
        float4 vb = *reinterpret_cast<const float4*>(g_h + (size_t)b * HID + lane * 4);
        acc.x += va.x + vb.x; acc.y += va.y + vb.y;
        acc.z += va.z + vb.z; acc.w += va.w + vb.w;
    }
    if (e < e1) {
        int a = __ldg(&g_csr_src[e]);
        float4 va = *reinterpret_cast<const float4*>(g_h + (size_t)a * HID + lane * 4);
        acc.x += va.x; acc.y += va.y; acc.z += va.z; acc.w += va.w;
    }
    float nd = __ldg(&g_norm_dst[n]);
    acc.x *= nd; acc.y *= nd; acc.z *= nd; acc.w *= nd;
    *reinterpret_cast<float4*>(agg + (size_t)n * HID + lane * 4) = acc;
}

// ---------------- GEMM: C[M,128] = epilogue( A[M,K] @ B[K,128] ) ----------------
// Block: 128 rows x 128 cols. 256 threads, 8x8 per thread, packed f32x2 FFMA.
__global__ __launch_bounds__(256)
void gemm_kernel(const float* __restrict__ A, int M, int K, int lda,
                 const float* __restrict__ B,          // [K][128] row-major
                 const float* __restrict__ bias,       // [128]
                 const float* __restrict__ out_scale,  // per-row or null
                 int apply_silu,
                 float* __restrict__ C,                // used if gids == null
                 const int* __restrict__ gids)         // pool mode if non-null
{
    __shared__ unsigned long long As2[8][128];  // A value duplicated into both halves
    __shared__ float              Bs [8][128];

    const int t    = threadIdx.x;
    const int tx   = t & 15;        // col group 0..15
    const int ty   = t >> 4;        // row group 0..15
    const int row0 = blockIdx.x * 128;

    const int arow = t >> 1;        // 0..127
    const int akl  = (t & 1) * 4;   // 0 or 4
    const int brow = t >> 5;        // 0..7
    const int bcol = (t & 31) * 4;  // 0..124

    const bool fast_a = (lda == 128);   // vector path: K==128, 16B aligned rows

    unsigned long long acc[8][4];
#pragma unroll
    for (int i = 0; i < 8; i++)
#pragma unroll
        for (int j = 0; j < 4; j++) acc[i][j] = 0ULL;

    for (int k0 = 0; k0 < K; k0 += 8) {
        // --- load A tile ---
        {
            int gr = row0 + arow;
            if (fast_a) {
                float4 a = make_float4(0.f, 0.f, 0.f, 0.f);
                if (gr < M) a = *reinterpret_cast<const float4*>(A + (size_t)gr * 128 + k0 + akl);
                unsigned long long p0, p1, p2, p3;
                asm("mov.b64 %0, {%1, %1};" : "=l"(p0) : "f"(a.x));
                asm("mov.b64 %0, {%1, %1};" : "=l"(p1) : "f"(a.y));
                asm("mov.b64 %0, {%1, %1};" : "=l"(p2) : "f"(a.z));
                asm("mov.b64 %0, {%1, %1};" : "=l"(p3) : "f"(a.w));
                As2[akl + 0][arow] = p0;
                As2[akl + 1][arow] = p1;
                As2[akl + 2][arow] = p2;
                As2[akl + 3][arow] = p3;
            } else {
#pragma unroll
                for (int i = 0; i < 4; i++) {
                    int kk = k0 + akl + i;
                    float a = 0.f;
                    if (gr < M && kk < K) a = __ldg(A + (size_t)gr * lda + kk);
                    unsigned long long pk;
                    asm("mov.b64 %0, {%1, %1};" : "=l"(pk) : "f"(a));
                    As2[akl + i][arow] = pk;
                }
            }
        }
        // --- load B tile ---
        {
            int kk = k0 + brow;
            float4 b = make_float4(0.f, 0.f, 0.f, 0.f);
            if (kk < K) b = *reinterpret_cast<const float4*>(B + (size_t)kk * 128 + bcol);
            *reinterpret_cast<float4*>(&Bs[brow][bcol]) = b;
        }
        __syncthreads();

#pragma unroll
        for (int k = 0; k < 8; k++) {
            ulonglong2 u0 = *reinterpret_cast<const ulonglong2*>(&Bs[k][tx * 4]);
            ulonglong2 u1 = *reinterpret_cast<const ulonglong2*>(&Bs[k][64 + tx * 4]);
            unsigned long long bp[4] = {u0.x, u0.y, u1.x, u1.y};
#pragma unroll
            for (int i = 0; i < 8; i++) {
                unsigned long long a2 = As2[k][ty * 8 + i];
#pragma unroll
                for (int j = 0; j < 4; j++)
                    asm("fma.rn.f32x2 %0, %1, %2, %0;"
                        : "+l"(acc[i][j]) : "l"(a2), "l"(bp[j]));
            }
        }
        __syncthreads();
    }

    // --- epilogue ---
    float4 bb0 = *reinterpret_cast<const float4*>(bias + tx * 4);
    float4 bb1 = *reinterpret_cast<const float4*>(bias + 64 + tx * 4);
    float bia[8] = {bb0.x, bb0.y, bb0.z, bb0.w, bb1.x, bb1.y, bb1.z, bb1.w};

    // pool-mode run-length state: graph_ids is sorted -> accumulate runs in regs
    int   curg = -1;
    float p[8];

#pragma unroll
    for (int i = 0; i < 8; i++) {
        int gr = row0 + ty * 8 + i;
        if (gr >= M) break;
        float os = out_scale ? __ldg(out_scale + gr) : 1.f;
        float v[8];
#pragma unroll
        for (int j = 0; j < 4; j++) {
            float lo, hi;
            asm("mov.b64 {%0, %1}, %2;" : "=f"(lo), "=f"(hi) : "l"(acc[i][j]));
            v[2 * j]     = lo;
            v[2 * j + 1] = hi;
        }
#pragma unroll
        for (int j = 0; j < 8; j++) {
            float w = v[j] + bia[j];
            if (apply_silu) w = w * (1.f / (1.f + __expf(-w)));
            v[j] = w * os;
        }
        if (gids) {
            int g = __ldg(gids + gr);
            if (g != curg) {
                if (curg >= 0) {
                    float* p0 = g_pooled + (size_t)curg * 128 + tx * 4;
                    asm volatile("red.global.add.v4.f32 [%0], {%1,%2,%3,%4};"
                                 :: "l"(p0), "f"(p[0]), "f"(p[1]), "f"(p[2]), "f"(p[3]) : "memory");
                    asm volatile("red.global.add.v4.f32 [%0], {%1,%2,%3,%4};"
                                 :: "l"(p0 + 64), "f"(p[4]), "f"(p[5]), "f"(p[6]), "f"(p[7]) : "memory");
                }
                curg = g;
#pragma unroll
                for (int j = 0; j < 8; j++) p[j] = v[j];
            } else {
#pragma unroll
                for (int j = 0; j < 8; j++) p[j] += v[j];
            }
        } else {
            *reinterpret_cast<float4*>(C + (size_t)gr * 128 + tx * 4) =
                make_float4(v[0], v[1], v[2], v[3]);
            *reinterpret_cast<float4*>(C + (size_t)gr * 128 + 64 + tx * 4) =
                make_float4(v[4], v[5], v[6], v[7]);
        }
    }
    if (gids && curg >= 0) {
        float* p0 = g_pooled + (size_t)curg * 128 + tx * 4;
        asm volatile("red.global.add.v4.f32 [%0], {%1,%2,%3,%4};"
                     :: "l"(p0), "f"(p[0]), "f"(p[1]), "f"(p[2]), "f"(p[3]) : "memory");
        asm volatile("red.global.add.v4.f32 [%0], {%1,%2,%3,%4};"
                     :: "l"(p0 + 64), "f"(p[4]), "f"(p[5]), "f"(p[6]), "f"(p[7]) : "memory");
    }
}

// ---------------- launch ----------------
extern "C" void kernel_launch(void* const* d_in, const int* in_sizes, int n_in,
                              void* d_out, int out_size) {
    const float* x     = (const float*)d_in[0];
    const int*   src   = (const int*)  d_in[1];
    const int*   dst   = (const int*)  d_in[2];
    const int*   gid   = (const int*)  d_in[3];
    const float* w_in  = (const float*)d_in[4];
    const float* b_in  = (const float*)d_in[5];
    const float* gw    = (const float*)d_in[6];
    const float* gb    = (const float*)d_in[7];
    const float* w_out = (const float*)d_in[8];
    const float* b_out = (const float*)d_in[9];
    const float* w_ff  = (const float*)d_in[10];
    const float* b_ff  = (const float*)d_in[11];
    float* out = (float*)d_out;

    float *h, *agg, *pooled, *nsrc;
    int *dgo, *dgi;
    cudaGetSymbolAddress((void**)&h,      g_h);
    cudaGetSymbolAddress((void**)&agg,    g_agg);
    cudaGetSymbolAddress((void**)&pooled, g_pooled);
    cudaGetSymbolAddress((void**)&nsrc,   g_norm_src);
    cudaGetSymbolAddress((void**)&dgo,    g_deg_out);
    cudaGetSymbolAddress((void**)&dgi,    g_deg_in);

    const int ZT = 256;
    zero4_kernel<<<(N_NODES / 4 + ZT - 1) / ZT, ZT>>>((float4*)dgo, N_NODES / 4);
    zero4_kernel<<<(N_NODES / 4 + ZT - 1) / ZT, ZT>>>((float4*)dgi, N_NODES / 4);
    zero4_kernel<<<(N_GRAPHS * HID / 4 + ZT - 1) / ZT, ZT>>>((float4*)pooled, N_GRAPHS * HID / 4);

    degree_kernel<<<(N_EDGES + 255) / 256, 256>>>(src, dst);
    norm_kernel<<<(N_NODES + 255) / 256, 256>>>();

    // CSR build (by dst): exclusive scan of deg_in -> row_ptr; cursor-fill csr_src
    scan1_kernel<<<N_SCANB, SCAN_B>>>();
    scan2_kernel<<<1, 256>>>();
    scan3_kernel<<<(N_NODES + 255) / 256, 256>>>();
    build_csr_kernel<<<(N_EDGES + 255) / 256, 256>>>(src, dst);

    const int rowTiles = (N_NODES + 127) / 128;  // 1563

    // h = silu(x @ w_in + b_in) * norm_src   (pre-scaled for SpMM gather)
    gemm_kernel<<<rowTiles, 256>>>(x, N_NODES, IN_F, IN_F, w_in, b_in,
                                   nsrc, 1, h, nullptr);

    for (int l = 0; l < 3; l++) {
        // agg = norm_dst * gather-sum(h)    (no atomics, no zeroing)
        gather_kernel<<<(N_NODES * 32 + 255) / 256, 256>>>(agg);
        // h = silu( agg @ gw[l] + gb[l] ) * (norm_src unless last layer)
        gemm_kernel<<<rowTiles, 256>>>(agg, N_NODES, HID, HID,
                                       gw + (size_t)l * HID * HID, gb + (size_t)l * HID,
                                       (l < 2) ? nsrc : nullptr, 1, h, nullptr);
    }

    // embedding_out + fused sum-pool: pooled[gid] += silu(h @ w_out + b_out)
    gemm_kernel<<<rowTiles, 256>>>(h, N_NODES, HID, HID, w_out, b_out,
                                   nullptr, 1, nullptr, gid);

    // out = pooled @ w_ff + b_ff
    gemm_kernel<<<(N_GRAPHS + 127) / 128, 256>>>(pooled, N_GRAPHS, HID, HID, w_ff, b_ff,
                                                 nullptr, 0, out, nullptr);
}

// round 5
// speedup vs baseline: 1.5274x; 1.0793x over previous
#include <cuda_runtime.h>

#define N_NODES  200000
#define N_EDGES  1600000
#define N_GRAPHS 10000
#define IN_F     74
#define HID      128

#define SCAN_B   1024
#define N_SCANB  ((N_NODES + SCAN_B - 1) / SCAN_B)   // 196

// ---------------- scratch (device globals; no allocation allowed) ----------------
__device__ __align__(16) float g_h  [(size_t)N_NODES * HID];
__device__ __align__(16) float g_agg[(size_t)N_NODES * HID];
__device__ __align__(16) int   g_deg_out[N_NODES];
__device__ __align__(16) int   g_deg_in [N_NODES];
__device__ __align__(16) float g_norm_src[N_NODES];
__device__ __align__(16) float g_norm_dst[N_NODES];
__device__ __align__(16) float g_pooled[(size_t)N_GRAPHS * HID];
__device__ __align__(16) int   g_row_ptr[N_NODES + 1];
__device__ __align__(16) int   g_cursor [N_NODES];
__device__ __align__(16) int   g_csr_src[N_EDGES];
__device__ __align__(16) int   g_bsums  [N_SCANB];

// fast silu: sigmoid via ex2.approx + rcp.approx (no IEEE div refinement).
// rcp(inf)=0 so large-negative inputs give exactly 0 (correct limit).
__device__ __forceinline__ float fast_silu(float w) {
    float t, r;
    asm("ex2.approx.f32 %0, %1;" : "=f"(t) : "f"(-1.4426950408889634f * w));
    asm("rcp.approx.f32 %0, %1;" : "=f"(r) : "f"(1.f + t));
    return w * r;
}

// ---------------- utility kernels ----------------
// zero deg_out, deg_in (ints) and pooled (floats) in one launch
__global__ void zero_all_kernel() {
    int i = blockIdx.x * blockDim.x + threadIdx.x;
    const int n_deg4 = N_NODES / 4;                 // 50000
    const int n_pool4 = N_GRAPHS * HID / 4;         // 320000
    if (i < n_deg4) {
        reinterpret_cast<int4*>(g_deg_out)[i] = make_int4(0, 0, 0, 0);
        reinterpret_cast<int4*>(g_deg_in )[i] = make_int4(0, 0, 0, 0);
    }
    if (i < n_pool4)
        reinterpret_cast<float4*>(g_pooled)[i] = make_float4(0.f, 0.f, 0.f, 0.f);
}

__global__ void degree_kernel(const int* __restrict__ src, const int* __restrict__ dst) {
    int i = blockIdx.x * blockDim.x + threadIdx.x;
    if (i < N_EDGES) {
        atomicAdd(&g_deg_out[src[i]], 1);
        atomicAdd(&g_deg_in [dst[i]], 1);
    }
}

__global__ void norm_kernel() {
    int i = blockIdx.x * blockDim.x + threadIdx.x;
    if (i < N_NODES) {
        g_norm_src[i] = rsqrtf(fmaxf((float)g_deg_out[i], 1.f));
        g_norm_dst[i] = rsqrtf(fmaxf((float)g_deg_in [i], 1.f));
    }
}

// ---------------- CSR build: exclusive scan of deg_in -> row_ptr ----------------
__global__ __launch_bounds__(SCAN_B) void scan1_kernel() {
    __shared__ int sh[SCAN_B];
    int i = blockIdx.x * SCAN_B + threadIdx.x;
    int v = (i < N_NODES) ? g_deg_in[i] : 0;
    sh[threadIdx.x] = v;
    __syncthreads();
#pragma unroll
    for (int off = 1; off < SCAN_B; off <<= 1) {
        int t = (threadIdx.x >= off) ? sh[threadIdx.x - off] : 0;
        __syncthreads();
        sh[threadIdx.x] += t;
        __syncthreads();
    }
    if (i < N_NODES) g_row_ptr[i] = sh[threadIdx.x] - v;   // exclusive, local
    if (threadIdx.x == SCAN_B - 1) g_bsums[blockIdx.x] = sh[threadIdx.x];
}

__global__ __launch_bounds__(256) void scan2_kernel() {
    __shared__ int sh[256];
    int v = (threadIdx.x < N_SCANB) ? g_bsums[threadIdx.x] : 0;
    sh[threadIdx.x] = v;
    __syncthreads();
#pragma unroll
    for (int off = 1; off < 256; off <<= 1) {
        int t = (threadIdx.x >= off) ? sh[threadIdx.x - off] : 0;
        __syncthreads();
        sh[threadIdx.x] += t;
        __syncthreads();
    }
    if (threadIdx.x < N_SCANB) g_bsums[threadIdx.x] = sh[threadIdx.x] - v;  // exclusive
}

__global__ void scan3_kernel() {
    int i = blockIdx.x * blockDim.x + threadIdx.x;
    if (i < N_NODES) {
        int rp = g_row_ptr[i] + g_bsums[i / SCAN_B];
        g_row_ptr[i] = rp;
        g_cursor [i] = rp;
    }
    if (i == 0) g_row_ptr[N_NODES] = N_EDGES;
}

__global__ void build_csr_kernel(const int* __restrict__ src, const int* __restrict__ dst) {
    int e = blockIdx.x * blockDim.x + threadIdx.x;
    if (e < N_EDGES) {
        int pos = atomicAdd(&g_cursor[dst[e]], 1);
        g_csr_src[pos] = src[e];
    }
}

// ---------------- SpMM gather: agg[n] = norm_dst[n] * sum_{e in in(n)} h[src_e]
// One warp per node; h rows are pre-scaled by norm_src. 4-way unrolled, 2 accumulators.
__global__ __launch_bounds__(256) void gather_kernel(float* __restrict__ agg) {
    int n    = (blockIdx.x * blockDim.x + threadIdx.x) >> 5;
    int lane = threadIdx.x & 31;
    if (n >= N_NODES) return;
    int e0 = __ldg(&g_row_ptr[n]);
    int e1 = __ldg(&g_row_ptr[n + 1]);
    float4 acc0 = make_float4(0.f, 0.f, 0.f, 0.f);
    float4 acc1 = make_float4(0.f, 0.f, 0.f, 0.f);
    int e = e0;
    for (; e + 4 <= e1; e += 4) {
        int i0 = __ldg(&g_csr_src[e]);
        int i1 = __ldg(&g_csr_src[e + 1]);
        int i2 = __ldg(&g_csr_src[e + 2]);
        int i3 = __ldg(&g_csr_src[e + 3]);
        float4 v0 = *reinterpret_cast<const float4*>(g_h + (size_t)i0 * HID + lane * 4);
        float4 v1 = *reinterpret_cast<const float4*>(g_h + (size_t)i1 * HID + lane * 4);
        float4 v2 = *reinterpret_cast<const float4*>(g_h + (size_t)i2 * HID + lane * 4);
        float4 v3 = *reinterpret_cast<const float4*>(g_h + (size_t)i3 * HID + lane * 4);
        acc0.x += v0.x + v1.x; acc0.y += v0.y + v1.y;
        acc0.z += v0.z + v1.z; acc0.w += v0.w + v1.w;
        acc1.x += v2.x + v3.x; acc1.y += v2.y + v3.y;
        acc1.z += v2.z + v3.z; acc1.w += v2.w + v3.w;
    }
    for (; e < e1; e++) {
        int a = __ldg(&g_csr_src[e]);
        float4 va = *reinterpret_cast<const float4*>(g_h + (size_t)a * HID + lane * 4);
        acc0.x += va.x; acc0.y += va.y; acc0.z += va.z; acc0.w += va.w;
    }
    float nd = __ldg(&g_norm_dst[n]);
    float4 acc;
    acc.x = (acc0.x + acc1.x) * nd;
    acc.y = (acc0.y + acc1.y) * nd;
    acc.z = (acc0.z + acc1.z) * nd;
    acc.w = (acc0.w + acc1.w) * nd;
    *reinterpret_cast<float4*>(agg + (size_t)n * HID + lane * 4) = acc;
}

// ---------------- GEMM: C[M,128] = epilogue( A[M,K] @ B[K,128] ) ----------------
// Block: 128 rows x 128 cols. 256 threads, 8x8 per thread, packed f32x2 FFMA.
__global__ __launch_bounds__(256)
void gemm_kernel(const float* __restrict__ A, int M, int K, int lda,
                 const float* __restrict__ B,          // [K][128] row-major
                 const float* __restrict__ bias,       // [128]
                 const float* __restrict__ out_scale,  // per-row or null
                 int apply_silu,
                 float* __restrict__ C,                // used if gids == null
                 const int* __restrict__ gids)         // pool mode if non-null
{
    __shared__ unsigned long long As2[8][128];  // A value duplicated into both halves
    __shared__ float              Bs [8][128];

    const int t    = threadIdx.x;
    const int tx   = t & 15;        // col group 0..15
    const int ty   = t >> 4;        // row group 0..15
    const int row0 = blockIdx.x * 128;

    const int arow = t >> 1;        // 0..127
    const int akl  = (t & 1) * 4;   // 0 or 4
    const int brow = t >> 5;        // 0..7
    const int bcol = (t & 31) * 4;  // 0..124

    const bool fast_a = (lda == 128);   // vector path: K==128, 16B aligned rows

    unsigned long long acc[8][4];
#pragma unroll
    for (int i = 0; i < 8; i++)
#pragma unroll
        for (int j = 0; j < 4; j++) acc[i][j] = 0ULL;

    for (int k0 = 0; k0 < K; k0 += 8) {
        // --- load A tile ---
        {
            int gr = row0 + arow;
            if (fast_a) {
                float4 a = make_float4(0.f, 0.f, 0.f, 0.f);
                if (gr < M) a = *reinterpret_cast<const float4*>(A + (size_t)gr * 128 + k0 + akl);
                unsigned long long p0, p1, p2, p3;
                asm("mov.b64 %0, {%1, %1};" : "=l"(p0) : "f"(a.x));
                asm("mov.b64 %0, {%1, %1};" : "=l"(p1) : "f"(a.y));
                asm("mov.b64 %0, {%1, %1};" : "=l"(p2) : "f"(a.z));
                asm("mov.b64 %0, {%1, %1};" : "=l"(p3) : "f"(a.w));
                As2[akl + 0][arow] = p0;
                As2[akl + 1][arow] = p1;
                As2[akl + 2][arow] = p2;
                As2[akl + 3][arow] = p3;
            } else {
#pragma unroll
                for (int i = 0; i < 4; i++) {
                    int kk = k0 + akl + i;
                    float a = 0.f;
                    if (gr < M && kk < K) a = __ldg(A + (size_t)gr * lda + kk);
                    unsigned long long pk;
                    asm("mov.b64 %0, {%1, %1};" : "=l"(pk) : "f"(a));
                    As2[akl + i][arow] = pk;
                }
            }
        }
        // --- load B tile ---
        {
            int kk = k0 + brow;
            float4 b = make_float4(0.f, 0.f, 0.f, 0.f);
            if (kk < K) b = *reinterpret_cast<const float4*>(B + (size_t)kk * 128 + bcol);
            *reinterpret_cast<float4*>(&Bs[brow][bcol]) = b;
        }
        __syncthreads();

#pragma unroll
        for (int k = 0; k < 8; k++) {
            // B: 2x LDS.128
            ulonglong2 u0 = *reinterpret_cast<const ulonglong2*>(&Bs[k][tx * 4]);
            ulonglong2 u1 = *reinterpret_cast<const ulonglong2*>(&Bs[k][64 + tx * 4]);
            unsigned long long bp[4] = {u0.x, u0.y, u1.x, u1.y};
            // A: 4x LDS.128 (broadcast across the 16 lanes sharing ty)
            const ulonglong2* ap = reinterpret_cast<const ulonglong2*>(&As2[k][ty * 8]);
            ulonglong2 a01 = ap[0], a23 = ap[1], a45 = ap[2], a67 = ap[3];
            unsigned long long av[8] = {a01.x, a01.y, a23.x, a23.y,
                                        a45.x, a45.y, a67.x, a67.y};
#pragma unroll
            for (int i = 0; i < 8; i++) {
#pragma unroll
                for (int j = 0; j < 4; j++)
                    asm("fma.rn.f32x2 %0, %1, %2, %0;"
                        : "+l"(acc[i][j]) : "l"(av[i]), "l"(bp[j]));
            }
        }
        __syncthreads();
    }

    // --- epilogue ---
    float4 bb0 = *reinterpret_cast<const float4*>(bias + tx * 4);
    float4 bb1 = *reinterpret_cast<const float4*>(bias + 64 + tx * 4);
    float bia[8] = {bb0.x, bb0.y, bb0.z, bb0.w, bb1.x, bb1.y, bb1.z, bb1.w};

    // pool-mode run-length state: graph_ids is sorted -> accumulate runs in regs
    int   curg = -1;
    float p[8];

#pragma unroll
    for (int i = 0; i < 8; i++) {
        int gr = row0 + ty * 8 + i;
        if (gr >= M) break;
        float os = out_scale ? __ldg(out_scale + gr) : 1.f;
        float v[8];
#pragma unroll
        for (int j = 0; j < 4; j++) {
            float lo, hi;
            asm("mov.b64 {%0, %1}, %2;" : "=f"(lo), "=f"(hi) : "l"(acc[i][j]));
            v[2 * j]     = lo;
            v[2 * j + 1] = hi;
        }
#pragma unroll
        for (int j = 0; j < 8; j++) {
            float w = v[j] + bia[j];
            if (apply_silu) w = fast_silu(w);
            v[j] = w * os;
        }
        if (gids) {
            int g = __ldg(gids + gr);
            if (g != curg) {
                if (curg >= 0) {
                    float* p0 = g_pooled + (size_t)curg * 128 + tx * 4;
                    asm volatile("red.global.add.v4.f32 [%0], {%1,%2,%3,%4};"
                                 :: "l"(p0), "f"(p[0]), "f"(p[1]), "f"(p[2]), "f"(p[3]) : "memory");
                    asm volatile("red.global.add.v4.f32 [%0], {%1,%2,%3,%4};"
                                 :: "l"(p0 + 64), "f"(p[4]), "f"(p[5]), "f"(p[6]), "f"(p[7]) : "memory");
                }
                curg = g;
#pragma unroll
                for (int j = 0; j < 8; j++) p[j] = v[j];
            } else {
#pragma unroll
                for (int j = 0; j < 8; j++) p[j] += v[j];
            }
        } else {
            *reinterpret_cast<float4*>(C + (size_t)gr * 128 + tx * 4) =
                make_float4(v[0], v[1], v[2], v[3]);
            *reinterpret_cast<float4*>(C + (size_t)gr * 128 + 64 + tx * 4) =
                make_float4(v[4], v[5], v[6], v[7]);
        }
    }
    if (gids && curg >= 0) {
        float* p0 = g_pooled + (size_t)curg * 128 + tx * 4;
        asm volatile("red.global.add.v4.f32 [%0], {%1,%2,%3,%4};"
                     :: "l"(p0), "f"(p[0]), "f"(p[1]), "f"(p[2]), "f"(p[3]) : "memory");
        asm volatile("red.global.add.v4.f32 [%0], {%1,%2,%3,%4};"
                     :: "l"(p0 + 64), "f"(p[4]), "f"(p[5]), "f"(p[6]), "f"(p[7]) : "memory");
    }
}

// ---------------- launch ----------------
extern "C" void kernel_launch(void* const* d_in, const int* in_sizes, int n_in,
                              void* d_out, int out_size) {
    const float* x     = (const float*)d_in[0];
    const int*   src   = (const int*)  d_in[1];
    const int*   dst   = (const int*)  d_in[2];
    const int*   gid   = (const int*)  d_in[3];
    const float* w_in  = (const float*)d_in[4];
    const float* b_in  = (const float*)d_in[5];
    const float* gw    = (const float*)d_in[6];
    const float* gb    = (const float*)d_in[7];
    const float* w_out = (const float*)d_in[8];
    const float* b_out = (const float*)d_in[9];
    const float* w_ff  = (const float*)d_in[10];
    const float* b_ff  = (const float*)d_in[11];
    float* out = (float*)d_out;

    float *h, *agg, *pooled, *nsrc;
    cudaGetSymbolAddress((void**)&h,      g_h);
    cudaGetSymbolAddress((void**)&agg,    g_agg);
    cudaGetSymbolAddress((void**)&pooled, g_pooled);
    cudaGetSymbolAddress((void**)&nsrc,   g_norm_src);

    const int rowTiles = (N_NODES + 127) / 128;  // 1563

    // launch order chosen so launch #4 is the big FFMA GEMM (for ncu -s capture)
    zero_all_kernel<<<(N_GRAPHS * HID / 4 + 255) / 256, 256>>>();                 // 1
    degree_kernel<<<(N_EDGES + 255) / 256, 256>>>(src, dst);                      // 2
    norm_kernel<<<(N_NODES + 255) / 256, 256>>>();                                // 3

    // h = silu(x @ w_in + b_in) * norm_src   (pre-scaled for SpMM gather)
    gemm_kernel<<<rowTiles, 256>>>(x, N_NODES, IN_F, IN_F, w_in, b_in,            // 4
                                   nsrc, 1, h, nullptr);

    // CSR build (by dst): exclusive scan of deg_in -> row_ptr; cursor-fill csr_src
    scan1_kernel<<<N_SCANB, SCAN_B>>>();                                          // 5
    scan2_kernel<<<1, 256>>>();                                                   // 6
    scan3_kernel<<<(N_NODES + 255) / 256, 256>>>();                               // 7
    build_csr_kernel<<<(N_EDGES + 255) / 256, 256>>>(src, dst);                   // 8

    for (int l = 0; l < 3; l++) {
        // agg = norm_dst * gather-sum(h)    (no atomics, no zeroing)
        gather_kernel<<<(N_NODES * 32 + 255) / 256, 256>>>(agg);
        // h = silu( agg @ gw[l] + gb[l] ) * (norm_src unless last layer)
        gemm_kernel<<<rowTiles, 256>>>(agg, N_NODES, HID, HID,
                                       gw + (size_t)l * HID * HID, gb + (size_t)l * HID,
                                       (l < 2) ? nsrc : nullptr, 1, h, nullptr);
    }

    // embedding_out + fused sum-pool: pooled[gid] += silu(h @ w_out + b_out)
    gemm_kernel<<<rowTiles, 256>>>(h, N_NODES, HID, HID, w_out, b_out,
                                   nullptr, 1, nullptr, gid);

    // out = pooled @ w_ff + b_ff
    gemm_kernel<<<(N_GRAPHS + 127) / 128, 256>>>(pooled, N_GRAPHS, HID, HID, w_ff, b_ff,
                                                 nullptr, 0, out, nullptr);
}

// round 7
// speedup vs baseline: 1.6996x; 1.1128x over previous
#include <cuda_runtime.h>

#define N_NODES  200000
#define N_EDGES  1600000
#define N_GRAPHS 10000
#define IN_F     74
#define HID      128

#define SCAN_B   1024
#define N_SCANB  ((N_NODES + SCAN_B - 1) / SCAN_B)   // 196

// ---------------- scratch (device globals; no allocation allowed) ----------------
__device__ __align__(16) float g_h  [(size_t)N_NODES * HID];
__device__ __align__(16) float g_agg[(size_t)N_NODES * HID];
__device__ __align__(16) int   g_deg_out[N_NODES];
__device__ __align__(16) int   g_deg_in [N_NODES];
__device__ __align__(16) float g_norm_src[N_NODES];
__device__ __align__(16) float g_norm_dst[N_NODES];
__device__ __align__(16) float g_pooled[(size_t)N_GRAPHS * HID];
__device__ __align__(16) int   g_row_ptr[N_NODES + 1];
__device__ __align__(16) int   g_cursor [N_NODES];
__device__ __align__(16) int   g_csr_src[N_EDGES];
__device__ __align__(16) int   g_bsums  [N_SCANB];

// fast silu: sigmoid via ex2.approx + rcp.approx. rcp(inf)=0 handles w->-inf.
__device__ __forceinline__ float fast_silu(float w) {
    float t, r;
    asm("ex2.approx.f32 %0, %1;" : "=f"(t) : "f"(-1.4426950408889634f * w));
    asm("rcp.approx.f32 %0, %1;" : "=f"(r) : "f"(1.f + t));
    return w * r;
}

// ---------------- utility kernels ----------------
__global__ void zero_all_kernel() {
    int i = blockIdx.x * blockDim.x + threadIdx.x;
    const int n_deg4 = N_NODES / 4;
    const int n_pool4 = N_GRAPHS * HID / 4;
    if (i < n_deg4) {
        reinterpret_cast<int4*>(g_deg_out)[i] = make_int4(0, 0, 0, 0);
        reinterpret_cast<int4*>(g_deg_in )[i] = make_int4(0, 0, 0, 0);
    }
    if (i < n_pool4)
        reinterpret_cast<float4*>(g_pooled)[i] = make_float4(0.f, 0.f, 0.f, 0.f);
}

__global__ void degree_kernel(const int* __restrict__ src, const int* __restrict__ dst) {
    int i = blockIdx.x * blockDim.x + threadIdx.x;
    if (i < N_EDGES) {
        atomicAdd(&g_deg_out[src[i]], 1);
        atomicAdd(&g_deg_in [dst[i]], 1);
    }
}

__global__ void norm_kernel() {
    int i = blockIdx.x * blockDim.x + threadIdx.x;
    if (i < N_NODES) {
        g_norm_src[i] = rsqrtf(fmaxf((float)g_deg_out[i], 1.f));
        g_norm_dst[i] = rsqrtf(fmaxf((float)g_deg_in [i], 1.f));
    }
}

// ---------------- CSR build ----------------
__global__ __launch_bounds__(SCAN_B) void scan1_kernel() {
    __shared__ int sh[SCAN_B];
    int i = blockIdx.x * SCAN_B + threadIdx.x;
    int v = (i < N_NODES) ? g_deg_in[i] : 0;
    sh[threadIdx.x] = v;
    __syncthreads();
#pragma unroll
    for (int off = 1; off < SCAN_B; off <<= 1) {
        int t = (threadIdx.x >= off) ? sh[threadIdx.x - off] : 0;
        __syncthreads();
        sh[threadIdx.x] += t;
        __syncthreads();
    }
    if (i < N_NODES) g_row_ptr[i] = sh[threadIdx.x] - v;
    if (threadIdx.x == SCAN_B - 1) g_bsums[blockIdx.x] = sh[threadIdx.x];
}

__global__ __launch_bounds__(256) void scan2_kernel() {
    __shared__ int sh[256];
    int v = (threadIdx.x < N_SCANB) ? g_bsums[threadIdx.x] : 0;
    sh[threadIdx.x] = v;
    __syncthreads();
#pragma unroll
    for (int off = 1; off < 256; off <<= 1) {
        int t = (threadIdx.x >= off) ? sh[threadIdx.x - off] : 0;
        __syncthreads();
        sh[threadIdx.x] += t;
        __syncthreads();
    }
    if (threadIdx.x < N_SCANB) g_bsums[threadIdx.x] = sh[threadIdx.x] - v;
}

__global__ void scan3_kernel() {
    int i = blockIdx.x * blockDim.x + threadIdx.x;
    if (i < N_NODES) {
        int rp = g_row_ptr[i] + g_bsums[i / SCAN_B];
        g_row_ptr[i] = rp;
        g_cursor [i] = rp;
    }
    if (i == 0) g_row_ptr[N_NODES] = N_EDGES;
}

__global__ void build_csr_kernel(const int* __restrict__ src, const int* __restrict__ dst) {
    int e = blockIdx.x * blockDim.x + threadIdx.x;
    if (e < N_EDGES) {
        int pos = atomicAdd(&g_cursor[dst[e]], 1);
        g_csr_src[pos] = src[e];
    }
}

// ---------------- SpMM gather ----------------
__global__ __launch_bounds__(256) void gather_kernel(float* __restrict__ agg) {
    int n    = (blockIdx.x * blockDim.x + threadIdx.x) >> 5;
    int lane = threadIdx.x & 31;
    if (n >= N_NODES) return;
    int e0 = __ldg(&g_row_ptr[n]);
    int e1 = __ldg(&g_row_ptr[n + 1]);
    float4 acc0 = make_float4(0.f, 0.f, 0.f, 0.f);
    float4 acc1 = make_float4(0.f, 0.f, 0.f, 0.f);
    int e = e0;
    for (; e + 4 <= e1; e += 4) {
        int i0 = __ldg(&g_csr_src[e]);
        int i1 = __ldg(&g_csr_src[e + 1]);
        int i2 = __ldg(&g_csr_src[e + 2]);
        int i3 = __ldg(&g_csr_src[e + 3]);
        float4 v0 = *reinterpret_cast<const float4*>(g_h + (size_t)i0 * HID + lane * 4);
        float4 v1 = *reinterpret_cast<const float4*>(g_h + (size_t)i1 * HID + lane * 4);
        float4 v2 = *reinterpret_cast<const float4*>(g_h + (size_t)i2 * HID + lane * 4);
        float4 v3 = *reinterpret_cast<const float4*>(g_h + (size_t)i3 * HID + lane * 4);
        acc0.x += v0.x + v1.x; acc0.y += v0.y + v1.y;
        acc0.z += v0.z + v1.z; acc0.w += v0.w + v1.w;
        acc1.x += v2.x + v3.x; acc1.y += v2.y + v3.y;
        acc1.z += v2.z + v3.z; acc1.w += v2.w + v3.w;
    }
    for (; e < e1; e++) {
        int a = __ldg(&g_csr_src[e]);
        float4 va = *reinterpret_cast<const float4*>(g_h + (size_t)a * HID + lane * 4);
        acc0.x += va.x; acc0.y += va.y; acc0.z += va.z; acc0.w += va.w;
    }
    float nd = __ldg(&g_norm_dst[n]);
    float4 acc;
    acc.x = (acc0.x + acc1.x) * nd;
    acc.y = (acc0.y + acc1.y) * nd;
    acc.z = (acc0.z + acc1.z) * nd;
    acc.w = (acc0.w + acc1.w) * nd;
    *reinterpret_cast<float4*>(agg + (size_t)n * HID + lane * 4) = acc;
}

// ---------------- GEMM: C[M,128] = epilogue( A[M,K] @ B[K,128] ) ----------------
// 128x128 tile, 256 threads, 8x8/thread, packed f32x2 FFMA.
// Software pipelined: double-buffered SMEM, next chunk's LDGs issued before
// computing the current chunk; one __syncthreads per 8-k chunk.
__global__ __launch_bounds__(256, 2)
void gemm_kernel(const float* __restrict__ A, int M, int K, int lda,
                 const float* __restrict__ B,          // [K][128] row-major
                 const float* __restrict__ bias,       // [128]
                 const float* __restrict__ out_scale,  // per-row or null
                 int apply_silu,
                 float* __restrict__ C,                // used if gids == null
                 const int* __restrict__ gids)         // pool mode if non-null
{
    __shared__ unsigned long long As2[2][8][128];  // A duplicated into both halves
    __shared__ float              Bs [2][8][128];

    const int t    = threadIdx.x;
    const int tx   = t & 15;
    const int ty   = t >> 4;
    const int row0 = blockIdx.x * 128;

    const int arow = t >> 1;        // 0..127
    const int akl  = (t & 1) * 4;   // 0 or 4
    const int brow = t >> 5;        // 0..7
    const int bcol = (t & 31) * 4;  // 0..124

    const bool fast_a = (lda == 128);
    const int  gr     = row0 + arow;

    unsigned long long acc[8][4];
#pragma unroll
    for (int i = 0; i < 8; i++)
#pragma unroll
        for (int j = 0; j < 4; j++) acc[i][j] = 0ULL;

    float4 aReg, bReg;

    // --- load chunk k0 into registers ---
    auto load_regs = [&](int k0) {
        if (fast_a) {
            aReg = (gr < M) ? *reinterpret_cast<const float4*>(A + (size_t)gr * 128 + k0 + akl)
                            : make_float4(0.f, 0.f, 0.f, 0.f);
        } else {
            // generic path: 2x guarded float2 (rows 8B-aligned when lda even; kk even)
            float va[4] = {0.f, 0.f, 0.f, 0.f};
            if (gr < M) {
#pragma unroll
                for (int i = 0; i < 4; i += 2) {
                    int kk = k0 + akl + i;
                    if (kk + 1 < K) {
                        float2 p = __ldg(reinterpret_cast<const float2*>(A + (size_t)gr * lda + kk));
                        va[i] = p.x; va[i + 1] = p.y;
                    } else if (kk < K) {
                        va[i] = __ldg(A + (size_t)gr * lda + kk);
                    }
                }
            }
            aReg = make_float4(va[0], va[1], va[2], va[3]);
        }
        int kk = k0 + brow;
        bReg = (kk < K) ? *reinterpret_cast<const float4*>(B + (size_t)kk * 128 + bcol)
                        : make_float4(0.f, 0.f, 0.f, 0.f);
    };

    auto store_smem = [&](int buf) {
        unsigned long long p0, p1, p2, p3;
        asm("mov.b64 %0, {%1, %1};" : "=l"(p0) : "f"(aReg.x));
        asm("mov.b64 %0, {%1, %1};" : "=l"(p1) : "f"(aReg.y));
        asm("mov.b64 %0, {%1, %1};" : "=l"(p2) : "f"(aReg.z));
        asm("mov.b64 %0, {%1, %1};" : "=l"(p3) : "f"(aReg.w));
        As2[buf][akl + 0][arow] = p0;
        As2[buf][akl + 1][arow] = p1;
        As2[buf][akl + 2][arow] = p2;
        As2[buf][akl + 3][arow] = p3;
        *reinterpret_cast<float4*>(&Bs[buf][brow][bcol]) = bReg;
    };

    const int nchunks = (K + 7) / 8;
    load_regs(0);
    store_smem(0);
    __syncthreads();

    int cur = 0;
    for (int c = 0; c < nchunks; c++) {
        const bool more = (c + 1 < nchunks);
        if (more) load_regs((c + 1) * 8);   // LDGs in flight during compute

#pragma unroll
        for (int k = 0; k < 8; k++) {
            ulonglong2 u0 = *reinterpret_cast<const ulonglong2*>(&Bs[cur][k][tx * 4]);
            ulonglong2 u1 = *reinterpret_cast<const ulonglong2*>(&Bs[cur][k][64 + tx * 4]);
            unsigned long long bp[4] = {u0.x, u0.y, u1.x, u1.y};
            const ulonglong2* ap = reinterpret_cast<const ulonglong2*>(&As2[cur][k][ty * 8]);
            ulonglong2 a01 = ap[0], a23 = ap[1], a45 = ap[2], a67 = ap[3];
            unsigned long long av[8] = {a01.x, a01.y, a23.x, a23.y,
                                        a45.x, a45.y, a67.x, a67.y};
#pragma unroll
            for (int i = 0; i < 8; i++)
#pragma unroll
                for (int j = 0; j < 4; j++)
                    asm("fma.rn.f32x2 %0, %1, %2, %0;"
                        : "+l"(acc[i][j]) : "l"(av[i]), "l"(bp[j]));
        }

        if (more) store_smem(cur ^ 1);
        __syncthreads();
        cur ^= 1;
    }

    // --- epilogue ---
    float4 bb0 = *reinterpret_cast<const float4*>(bias + tx * 4);
    float4 bb1 = *reinterpret_cast<const float4*>(bias + 64 + tx * 4);
    float bia[8] = {bb0.x, bb0.y, bb0.z, bb0.w, bb1.x, bb1.y, bb1.z, bb1.w};

    int   curg = -1;
    float p[8];

#pragma unroll
    for (int i = 0; i < 8; i++) {
        int r = row0 + ty * 8 + i;
        if (r >= M) break;
        float os = out_scale ? __ldg(out_scale + r) : 1.f;
        float v[8];
#pragma unroll
        for (int j = 0; j < 4; j++) {
            float lo, hi;
            asm("mov.b64 {%0, %1}, %2;" : "=f"(lo), "=f"(hi) : "l"(acc[i][j]));
            v[2 * j]     = lo;
            v[2 * j + 1] = hi;
        }
#pragma unroll
        for (int j = 0; j < 8; j++) {
            float w = v[j] + bia[j];
            if (apply_silu) w = fast_silu(w);
            v[j] = w * os;
        }
        if (gids) {
            int g = __ldg(gids + r);
            if (g != curg) {
                if (curg >= 0) {
                    float* p0 = g_pooled + (size_t)curg * 128 + tx * 4;
                    asm volatile("red.global.add.v4.f32 [%0], {%1,%2,%3,%4};"
                                 :: "l"(p0), "f"(p[0]), "f"(p[1]), "f"(p[2]), "f"(p[3]) : "memory");
                    asm volatile("red.global.add.v4.f32 [%0], {%1,%2,%3,%4};"
                                 :: "l"(p0 + 64), "f"(p[4]), "f"(p[5]), "f"(p[6]), "f"(p[7]) : "memory");
                }
                curg = g;
#pragma unroll
                for (int j = 0; j < 8; j++) p[j] = v[j];
            } else {
#pragma unroll
                for (int j = 0; j < 8; j++) p[j] += v[j];
            }
        } else {
            *reinterpret_cast<float4*>(C + (size_t)r * 128 + tx * 4) =
                make_float4(v[0], v[1], v[2], v[3]);
            *reinterpret_cast<float4*>(C + (size_t)r * 128 + 64 + tx * 4) =
                make_float4(v[4], v[5], v[6], v[7]);
        }
    }
    if (gids && curg >= 0) {
        float* p0 = g_pooled + (size_t)curg * 128 + tx * 4;
        asm volatile("red.global.add.v4.f32 [%0], {%1,%2,%3,%4};"
                     :: "l"(p0), "f"(p[0]), "f"(p[1]), "f"(p[2]), "f"(p[3]) : "memory");
        asm volatile("red.global.add.v4.f32 [%0], {%1,%2,%3,%4};"
                     :: "l"(p0 + 64), "f"(p[4]), "f"(p[5]), "f"(p[6]), "f"(p[7]) : "memory");
    }
}

// ---------------- launch ----------------
extern "C" void kernel_launch(void* const* d_in, const int* in_sizes, int n_in,
                              void* d_out, int out_size) {
    const float* x     = (const float*)d_in[0];
    const int*   src   = (const int*)  d_in[1];
    const int*   dst   = (const int*)  d_in[2];
    const int*   gid   = (const int*)  d_in[3];
    const float* w_in  = (const float*)d_in[4];
    const float* b_in  = (const float*)d_in[5];
    const float* gw    = (const float*)d_in[6];
    const float* gb    = (const float*)d_in[7];
    const float* w_out = (const float*)d_in[8];
    const float* b_out = (const float*)d_in[9];
    const float* w_ff  = (const float*)d_in[10];
    const float* b_ff  = (const float*)d_in[11];
    float* out = (float*)d_out;

    float *h, *agg, *pooled, *nsrc;
    cudaGetSymbolAddress((void**)&h,      g_h);
    cudaGetSymbolAddress((void**)&agg,    g_agg);
    cudaGetSymbolAddress((void**)&pooled, g_pooled);
    cudaGetSymbolAddress((void**)&nsrc,   g_norm_src);

    const int rowTiles = (N_NODES + 127) / 128;  // 1563

    // launch order keeps the FFMA GEMM at position 4 for ncu capture
    zero_all_kernel<<<(N_GRAPHS * HID / 4 + 255) / 256, 256>>>();                 // 1
    degree_kernel<<<(N_EDGES + 255) / 256, 256>>>(src, dst);                      // 2
    norm_kernel<<<(N_NODES + 255) / 256, 256>>>();                                // 3

    // h = silu(x @ w_in + b_in) * norm_src
    gemm_kernel<<<rowTiles, 256>>>(x, N_NODES, IN_F, IN_F, w_in, b_in,            // 4
                                   nsrc, 1, h, nullptr);

    // CSR build (by dst)
    scan1_kernel<<<N_SCANB, SCAN_B>>>();                                          // 5
    scan2_kernel<<<1, 256>>>();                                                   // 6
    scan3_kernel<<<(N_NODES + 255) / 256, 256>>>();                               // 7
    build_csr_kernel<<<(N_EDGES + 255) / 256, 256>>>(src, dst);                   // 8

    for (int l = 0; l < 3; l++) {
        gather_kernel<<<(N_NODES * 32 + 255) / 256, 256>>>(agg);
        gemm_kernel<<<rowTiles, 256>>>(agg, N_NODES, HID, HID,
                                       gw + (size_t)l * HID * HID, gb + (size_t)l * HID,
                                       (l < 2) ? nsrc : nullptr, 1, h, nullptr);
    }

    // embedding_out + fused sum-pool
    gemm_kernel<<<rowTiles, 256>>>(h, N_NODES, HID, HID, w_out, b_out,
                                   nullptr, 1, nullptr, gid);

    // out = pooled @ w_ff + b_ff
    gemm_kernel<<<(N_GRAPHS + 127) / 128, 256>>>(pooled, N_GRAPHS, HID, HID, w_ff, b_ff,
                                                 nullptr, 0, out, nullptr);
}

// round 9
// speedup vs baseline: 1.9362x; 1.1392x over previous
#include <cuda_runtime.h>
#include <cuda_bf16.h>
#include <cstdint>

#define N_NODES  200000
#define N_EDGES  1600000
#define N_GRAPHS 10000
#define IN_F     74
#define HID      128

#define SCAN_B   1024
#define N_SCANB  ((N_NODES + SCAN_B - 1) / SCAN_B)   // 196

// ---------------- scratch (device globals; no allocation allowed) ----------------
__device__ __align__(16) __nv_bfloat16 g_h_hi  [(size_t)N_NODES * HID];
__device__ __align__(16) __nv_bfloat16 g_h_lo  [(size_t)N_NODES * HID];
__device__ __align__(16) __nv_bfloat16 g_agg_hi[(size_t)N_NODES * HID];
__device__ __align__(16) __nv_bfloat16 g_agg_lo[(size_t)N_NODES * HID];
__device__ __align__(16) __nv_bfloat16 g_wt_hi [4 * HID * HID];   // [l][n][k] = W_l[k][n]
__device__ __align__(16) __nv_bfloat16 g_wt_lo [4 * HID * HID];
__device__ __align__(16) int   g_deg_out[N_NODES];
__device__ __align__(16) int   g_deg_in [N_NODES];
__device__ __align__(16) float g_norm_src[N_NODES];
__device__ __align__(16) float g_norm_dst[N_NODES];
__device__ __align__(16) float g_pooled[(size_t)N_GRAPHS * HID];
__device__ __align__(16) int   g_row_ptr[N_NODES + 1];
__device__ __align__(16) int   g_cursor [N_NODES];
__device__ __align__(16) int   g_csr_src[N_EDGES];
__device__ __align__(16) int   g_bsums  [N_SCANB];

// fast silu: sigmoid via ex2.approx + rcp.approx. rcp(inf)=0 handles w->-inf.
__device__ __forceinline__ float fast_silu(float w) {
    float t, r;
    asm("ex2.approx.f32 %0, %1;" : "=f"(t) : "f"(-1.4426950408889634f * w));
    asm("rcp.approx.f32 %0, %1;" : "=f"(r) : "f"(1.f + t));
    return w * r;
}

__device__ __forceinline__ uint32_t smem_u32(const void* p) {
    uint32_t a;
    asm("{ .reg .u64 t; cvta.to.shared.u64 t, %1; cvt.u32.u64 %0, t; }" : "=r"(a) : "l"(p));
    return a;
}

#define LDSM4(r, addr)                                                          \
    asm volatile("ldmatrix.sync.aligned.m8n8.x4.shared.b16 {%0,%1,%2,%3}, [%4];" \
                 : "=r"((r)[0]), "=r"((r)[1]), "=r"((r)[2]), "=r"((r)[3])        \
                 : "r"(addr))

#define MMA16816(c, a, b)                                                        \
    asm volatile("mma.sync.aligned.m16n8k16.row.col.f32.bf16.bf16.f32 "          \
                 "{%0,%1,%2,%3}, {%4,%5,%6,%7}, {%8,%9}, {%0,%1,%2,%3};"         \
                 : "+f"((c)[0]), "+f"((c)[1]), "+f"((c)[2]), "+f"((c)[3])        \
                 : "r"((a)[0]), "r"((a)[1]), "r"((a)[2]), "r"((a)[3]),           \
                   "r"((b)[0]), "r"((b)[1]))

// ---------------- setup: zero counters/pooled + transpose/split weights ----------------
__global__ void prep_kernel(const float* __restrict__ gw, const float* __restrict__ w_out) {
    int i = blockIdx.x * blockDim.x + threadIdx.x;
    const int n_deg4 = N_NODES / 4;
    const int n_pool4 = N_GRAPHS * HID / 4;
    if (i < n_deg4) {
        reinterpret_cast<int4*>(g_deg_out)[i] = make_int4(0, 0, 0, 0);
        reinterpret_cast<int4*>(g_deg_in )[i] = make_int4(0, 0, 0, 0);
    }
    if (i < n_pool4)
        reinterpret_cast<float4*>(g_pooled)[i] = make_float4(0.f, 0.f, 0.f, 0.f);
    if (i < 4 * HID * HID) {
        int l = i >> 14, n = (i >> 7) & 127, k = i & 127;
        float v = (l < 3) ? gw[l * HID * HID + k * HID + n] : w_out[k * HID + n];
        __nv_bfloat16 hb = __float2bfloat16(v);
        g_wt_hi[i] = hb;
        g_wt_lo[i] = __float2bfloat16(v - __bfloat162float(hb));
    }
}

__global__ void degree_kernel(const int* __restrict__ src, const int* __restrict__ dst) {
    int i = blockIdx.x * blockDim.x + threadIdx.x;
    if (i < N_EDGES) {
        atomicAdd(&g_deg_out[src[i]], 1);
        atomicAdd(&g_deg_in [dst[i]], 1);
    }
}

__global__ void norm_kernel() {
    int i = blockIdx.x * blockDim.x + threadIdx.x;
    if (i < N_NODES) {
        g_norm_src[i] = rsqrtf(fmaxf((float)g_deg_out[i], 1.f));
        g_norm_dst[i] = rsqrtf(fmaxf((float)g_deg_in [i], 1.f));
    }
}

// ---------------- CSR build ----------------
__global__ __launch_bounds__(SCAN_B) void scan1_kernel() {
    __shared__ int sh[SCAN_B];
    int i = blockIdx.x * SCAN_B + threadIdx.x;
    int v = (i < N_NODES) ? g_deg_in[i] : 0;
    sh[threadIdx.x] = v;
    __syncthreads();
#pragma unroll
    for (int off = 1; off < SCAN_B; off <<= 1) {
        int t = (threadIdx.x >= off) ? sh[threadIdx.x - off] : 0;
        __syncthreads();
        sh[threadIdx.x] += t;
        __syncthreads();
    }
    if (i < N_NODES) g_row_ptr[i] = sh[threadIdx.x] - v;
    if (threadIdx.x == SCAN_B - 1) g_bsums[blockIdx.x] = sh[threadIdx.x];
}

__global__ __launch_bounds__(256) void scan2_kernel() {
    __shared__ int sh[256];
    int v = (threadIdx.x < N_SCANB) ? g_bsums[threadIdx.x] : 0;
    sh[threadIdx.x] = v;
    __syncthreads();
#pragma unroll
    for (int off = 1; off < 256; off <<= 1) {
        int t = (threadIdx.x >= off) ? sh[threadIdx.x - off] : 0;
        __syncthreads();
        sh[threadIdx.x] += t;
        __syncthreads();
    }
    if (threadIdx.x < N_SCANB) g_bsums[threadIdx.x] = sh[threadIdx.x] - v;
}

__global__ void scan3_kernel() {
    int i = blockIdx.x * blockDim.x + threadIdx.x;
    if (i < N_NODES) {
        int rp = g_row_ptr[i] + g_bsums[i / SCAN_B];
        g_row_ptr[i] = rp;
        g_cursor [i] = rp;
    }
    if (i == 0) g_row_ptr[N_NODES] = N_EDGES;
}

__global__ void build_csr_kernel(const int* __restrict__ src, const int* __restrict__ dst) {
    int e = blockIdx.x * blockDim.x + threadIdx.x;
    if (e < N_EDGES) {
        int pos = atomicAdd(&g_cursor[dst[e]], 1);
        g_csr_src[pos] = src[e];
    }
}

// ---------------- SpMM gather (split bf16 in/out) ----------------
__global__ __launch_bounds__(256) void gather_kernel() {
    int n    = (blockIdx.x * blockDim.x + threadIdx.x) >> 5;
    int lane = threadIdx.x & 31;
    if (n >= N_NODES) return;
    int e0 = __ldg(&g_row_ptr[n]);
    int e1 = __ldg(&g_row_ptr[n + 1]);
    float v0 = 0.f, v1 = 0.f, v2 = 0.f, v3 = 0.f;
    float u0 = 0.f, u1 = 0.f, u2 = 0.f, u3 = 0.f;
    int e = e0;
    for (; e + 2 <= e1; e += 2) {
        int a = __ldg(&g_csr_src[e]);
        int b = __ldg(&g_csr_src[e + 1]);
        size_t oa = (size_t)a * HID + lane * 4;
        size_t ob = (size_t)b * HID + lane * 4;
        uint2 rha = *reinterpret_cast<const uint2*>(g_h_hi + oa);
        uint2 rla = *reinterpret_cast<const uint2*>(g_h_lo + oa);
        uint2 rhb = *reinterpret_cast<const uint2*>(g_h_hi + ob);
        uint2 rlb = *reinterpret_cast<const uint2*>(g_h_lo + ob);
        __nv_bfloat162 ha0 = *reinterpret_cast<__nv_bfloat162*>(&rha.x);
        __nv_bfloat162 ha1 = *reinterpret_cast<__nv_bfloat162*>(&rha.y);
        __nv_bfloat162 la0 = *reinterpret_cast<__nv_bfloat162*>(&rla.x);
        __nv_bfloat162 la1 = *reinterpret_cast<__nv_bfloat162*>(&rla.y);
        __nv_bfloat162 hb0 = *reinterpret_cast<__nv_bfloat162*>(&rhb.x);
        __nv_bfloat162 hb1 = *reinterpret_cast<__nv_bfloat162*>(&rhb.y);
        __nv_bfloat162 lb0 = *reinterpret_cast<__nv_bfloat162*>(&rlb.x);
        __nv_bfloat162 lb1 = *reinterpret_cast<__nv_bfloat162*>(&rlb.y);
        v0 += __bfloat162float(ha0.x) + __bfloat162float(la0.x);
        v1 += __bfloat162float(ha0.y) + __bfloat162float(la0.y);
        v2 += __bfloat162float(ha1.x) + __bfloat162float(la1.x);
        v3 += __bfloat162float(ha1.y) + __bfloat162float(la1.y);
        u0 += __bfloat162float(hb0.x) + __bfloat162float(lb0.x);
        u1 += __bfloat162float(hb0.y) + __bfloat162float(lb0.y);
        u2 += __bfloat162float(hb1.x) + __bfloat162float(lb1.x);
        u3 += __bfloat162float(hb1.y) + __bfloat162float(lb1.y);
    }
    if (e < e1) {
        int a = __ldg(&g_csr_src[e]);
        size_t oa = (size_t)a * HID + lane * 4;
        uint2 rha = *reinterpret_cast<const uint2*>(g_h_hi + oa);
        uint2 rla = *reinterpret_cast<const uint2*>(g_h_lo + oa);
        __nv_bfloat162 ha0 = *reinterpret_cast<__nv_bfloat162*>(&rha.x);
        __nv_bfloat162 ha1 = *reinterpret_cast<__nv_bfloat162*>(&rha.y);
        __nv_bfloat162 la0 = *reinterpret_cast<__nv_bfloat162*>(&rla.x);
        __nv_bfloat162 la1 = *reinterpret_cast<__nv_bfloat162*>(&rla.y);
        v0 += __bfloat162float(ha0.x) + __bfloat162float(la0.x);
        v1 += __bfloat162float(ha0.y) + __bfloat162float(la0.y);
        v2 += __bfloat162float(ha1.x) + __bfloat162float(la1.x);
        v3 += __bfloat162float(ha1.y) + __bfloat162float(la1.y);
    }
    float nd = __ldg(&g_norm_dst[n]);
    float w[4] = {(v0 + u0) * nd, (v1 + u1) * nd, (v2 + u2) * nd, (v3 + u3) * nd};
    unsigned short hs[4], ls[4];
#pragma unroll
    for (int j = 0; j < 4; j++) {
        __nv_bfloat16 hb = __float2bfloat16(w[j]);
        hs[j] = __bfloat16_as_ushort(hb);
        ls[j] = __bfloat16_as_ushort(__float2bfloat16(w[j] - __bfloat162float(hb)));
    }
    size_t o = (size_t)n * HID + lane * 4;
    uint2 ph, pl;
    ph.x = (uint32_t)hs[0] | ((uint32_t)hs[1] << 16);
    ph.y = (uint32_t)hs[2] | ((uint32_t)hs[3] << 16);
    pl.x = (uint32_t)ls[0] | ((uint32_t)ls[1] << 16);
    pl.y = (uint32_t)ls[2] | ((uint32_t)ls[3] << 16);
    *reinterpret_cast<uint2*>(g_agg_hi + o) = ph;
    *reinterpret_cast<uint2*>(g_agg_lo + o) = pl;
}

// ---------------- HMMA GEMM: D[128,128] = (Ah+Al) @ (Wh+Wl), 3-term split ----------------
// mma.sync m16n8k16 bf16 (portable PTX). 8 warps: 4(M)x2(N), each 32x64.
// SMEM rows padded to 272B (conflict-free ldmatrix). Staged via cp.async.bulk.
#define TROW 272
#define OFF_MBAR 0
#define OFF_BIAS 16
#define OFF_AHI  1024
#define OFF_ALO  (OFF_AHI + 128 * TROW)
#define OFF_WHI  (OFF_ALO + 128 * TROW)
#define OFF_WLO  (OFF_WHI + 128 * TROW)
#define TG_SMEM  (OFF_WLO + 128 * TROW)

__global__ __launch_bounds__(256)
void tgemm_kernel(const __nv_bfloat16* __restrict__ a_hi,
                  const __nv_bfloat16* __restrict__ a_lo,
                  const __nv_bfloat16* __restrict__ w_hi,
                  const __nv_bfloat16* __restrict__ w_lo,
                  const float* __restrict__ bias,
                  const float* __restrict__ out_scale,
                  __nv_bfloat16* __restrict__ o_hi,
                  __nv_bfloat16* __restrict__ o_lo,
                  const int* __restrict__ gids)
{
    extern __shared__ char smem[];
    uint32_t sb = smem_u32(smem);
    const int tid = threadIdx.x, wid = tid >> 5, lane = tid & 31;
    const int row0 = blockIdx.x * 128;
    const int valid = min(128, N_NODES - row0);

    if (tid == 0)
        asm volatile("mbarrier.init.shared.b64 [%0], %1;" :: "r"(sb + OFF_MBAR), "r"(1u) : "memory");
    if (tid < 128) ((float*)(smem + OFF_BIAS))[tid] = bias[tid];
    __syncthreads();

    if (tid == 0) {
        uint32_t tx = (uint32_t)(256 + 2 * valid) * 256;
        asm volatile("mbarrier.arrive.expect_tx.shared.b64 _, [%0], %1;"
                     :: "r"(sb + OFF_MBAR), "r"(tx) : "memory");
    }
    // 512 row-copies of 256B: arrays {Whi, Wlo, Ahi, Alo} x 128 rows
    for (int p = tid; p < 512; p += 256) {
        int arr = p >> 7, row = p & 127;
        uint32_t dst;
        const char* src;
        bool ok = true;
        if (arr == 0)      { dst = sb + OFF_WHI + row * TROW; src = (const char*)w_hi + row * 256; }
        else if (arr == 1) { dst = sb + OFF_WLO + row * TROW; src = (const char*)w_lo + row * 256; }
        else {
            ok = row < valid;
            size_t go = (size_t)(row0 + row) * 256;
            if (arr == 2) { dst = sb + OFF_AHI + row * TROW; src = (const char*)a_hi + go; }
            else          { dst = sb + OFF_ALO + row * TROW; src = (const char*)a_lo + go; }
        }
        if (ok)
            asm volatile("cp.async.bulk.shared::cluster.global.mbarrier::complete_tx::bytes "
                         "[%0], [%1], %2, [%3];"
                         :: "r"(dst), "l"(src), "r"(256u), "r"(sb + OFF_MBAR) : "memory");
    }
    // wait for all bulk copies
    {
        uint32_t mb = sb + OFF_MBAR, done;
        asm volatile("{\n\t.reg .pred p;\n\t"
                     "mbarrier.try_wait.parity.acquire.cta.shared::cta.b64 p, [%1], 0;\n\t"
                     "selp.b32 %0, 1, 0, p;\n\t}" : "=r"(done) : "r"(mb) : "memory");
        if (!done) {
            asm volatile("{\n\t.reg .pred P1;\n\t"
                         "WL_%=:\n\t"
                         "mbarrier.try_wait.parity.acquire.cta.shared::cta.b64 P1, [%0], 0, 0x989680;\n\t"
                         "@P1 bra.uni WD_%=;\n\t"
                         "bra.uni WL_%=;\n\t"
                         "WD_%=:\n\t}" :: "r"(mb) : "memory");
        }
    }
    __syncthreads();

    const int wm = wid >> 1;          // 0..3 -> rows wm*32
    const int wn = wid & 1;           // 0..1 -> cols wn*64
    const int r0 = wm * 32, n0 = wn * 64;

    float acc[2][8][4];
#pragma unroll
    for (int m = 0; m < 2; m++)
#pragma unroll
        for (int j = 0; j < 8; j++)
#pragma unroll
            for (int q = 0; q < 4; q++) acc[m][j][q] = 0.f;

    const int arow = lane & 15;
    const int akb  = (lane >> 4) << 4;
    const int bn   = (lane & 7) + ((lane >> 4) << 3);
    const int bkb  = ((lane >> 3) & 1) << 4;

#pragma unroll
    for (int ks = 0; ks < 8; ks++) {
        uint32_t ah[2][4], al[2][4], bh[8][2], bl[8][2];
#pragma unroll
        for (int m = 0; m < 2; m++) {
            uint32_t ad = sb + OFF_AHI + (uint32_t)(r0 + m * 16 + arow) * TROW + ks * 32 + akb;
            LDSM4(ah[m], ad);
            LDSM4(al[m], ad + (OFF_ALO - OFF_AHI));
        }
#pragma unroll
        for (int jp = 0; jp < 4; jp++) {
            uint32_t bd = sb + OFF_WHI + (uint32_t)(n0 + jp * 16 + bn) * TROW + ks * 32 + bkb;
            uint32_t r[4];
            LDSM4(r, bd);
            bh[2 * jp][0] = r[0]; bh[2 * jp][1] = r[1];
            bh[2 * jp + 1][0] = r[2]; bh[2 * jp + 1][1] = r[3];
            LDSM4(r, bd + (OFF_WLO - OFF_WHI));
            bl[2 * jp][0] = r[0]; bl[2 * jp][1] = r[1];
            bl[2 * jp + 1][0] = r[2]; bl[2 * jp + 1][1] = r[3];
        }
#pragma unroll
        for (int m = 0; m < 2; m++)
#pragma unroll
            for (int j = 0; j < 8; j++) {
                MMA16816(acc[m][j], ah[m], bh[j]);
                MMA16816(acc[m][j], ah[m], bl[j]);
                MMA16816(acc[m][j], al[m], bh[j]);
            }
    }

    // ---- epilogue ----
    const float* bs = (const float*)(smem + OFF_BIAS);
    const int cp = n0 + (lane & 3) * 2;   // col pair base
#pragma unroll
    for (int m = 0; m < 2; m++) {
#pragma unroll
        for (int hf = 0; hf < 2; hf++) {
            int gr = row0 + r0 + m * 16 + hf * 8 + (lane >> 2);
            if (gr >= N_NODES) continue;
            if (gids) {
                int g = __ldg(gids + gr);
                float* pb = g_pooled + (size_t)g * 128 + cp;
#pragma unroll
                for (int j = 0; j < 8; j++) {
                    int c = cp + j * 8;
                    float va = fast_silu(acc[m][j][hf * 2 + 0] + bs[c]);
                    float vb = fast_silu(acc[m][j][hf * 2 + 1] + bs[c + 1]);
                    asm volatile("red.global.add.v2.f32 [%0], {%1,%2};"
                                 :: "l"(pb + j * 8), "f"(va), "f"(vb) : "memory");
                }
            } else {
                float os = out_scale ? __ldg(out_scale + gr) : 1.f;
#pragma unroll
                for (int j = 0; j < 8; j++) {
                    int c = cp + j * 8;
                    float va = fast_silu(acc[m][j][hf * 2 + 0] + bs[c]) * os;
                    float vb = fast_silu(acc[m][j][hf * 2 + 1] + bs[c + 1]) * os;
                    __nv_bfloat16 ha = __float2bfloat16(va);
                    __nv_bfloat16 hb = __float2bfloat16(vb);
                    uint32_t uh = (uint32_t)__bfloat16_as_ushort(ha)
                                | ((uint32_t)__bfloat16_as_ushort(hb) << 16);
                    uint32_t ul = (uint32_t)__bfloat16_as_ushort(__float2bfloat16(va - __bfloat162float(ha)))
                                | ((uint32_t)__bfloat16_as_ushort(__float2bfloat16(vb - __bfloat162float(hb))) << 16);
                    size_t o = (size_t)gr * 128 + c;
                    *reinterpret_cast<uint32_t*>(o_hi + o) = uh;
                    *reinterpret_cast<uint32_t*>(o_lo + o) = ul;
                }
            }
        }
    }
    __syncthreads();
    if (tid == 0)
        asm volatile("mbarrier.inval.shared.b64 [%0];" :: "r"(sb + OFF_MBAR) : "memory");
}

// ---------------- FFMA GEMM (K=74 input layer; final w_ff) ----------------
__global__ __launch_bounds__(256, 2)
void gemm_kernel(const float* __restrict__ A, int M, int K, int lda,
                 const float* __restrict__ B, const float* __restrict__ bias,
                 const float* __restrict__ out_scale, int apply_silu,
                 float* __restrict__ C,
                 __nv_bfloat16* __restrict__ Ch,
                 __nv_bfloat16* __restrict__ Cl)
{
    __shared__ unsigned long long As2[2][8][128];
    __shared__ float              Bs [2][8][128];

    const int t    = threadIdx.x;
    const int tx   = t & 15;
    const int ty   = t >> 4;
    const int row0 = blockIdx.x * 128;

    const int arow = t >> 1;
    const int akl  = (t & 1) * 4;
    const int brow = t >> 5;
    const int bcol = (t & 31) * 4;

    const bool fast_a = (lda == 128);
    const int  gr     = row0 + arow;

    unsigned long long acc[8][4];
#pragma unroll
    for (int i = 0; i < 8; i++)
#pragma unroll
        for (int j = 0; j < 4; j++) acc[i][j] = 0ULL;

    float4 aReg, bReg;

    auto load_regs = [&](int k0) {
        if (fast_a) {
            aReg = (gr < M) ? *reinterpret_cast<const float4*>(A + (size_t)gr * 128 + k0 + akl)
                            : make_float4(0.f, 0.f, 0.f, 0.f);
        } else {
            float va[4] = {0.f, 0.f, 0.f, 0.f};
            if (gr < M) {
#pragma unroll
                for (int i = 0; i < 4; i += 2) {
                    int kk = k0 + akl + i;
                    if (kk + 1 < K) {
                        float2 p = __ldg(reinterpret_cast<const float2*>(A + (size_t)gr * lda + kk));
                        va[i] = p.x; va[i + 1] = p.y;
                    } else if (kk < K) {
                        va[i] = __ldg(A + (size_t)gr * lda + kk);
                    }
                }
            }
            aReg = make_float4(va[0], va[1], va[2], va[3]);
        }
        int kk = k0 + brow;
        bReg = (kk < K) ? *reinterpret_cast<const float4*>(B + (size_t)kk * 128 + bcol)
                        : make_float4(0.f, 0.f, 0.f, 0.f);
    };

    auto store_smem = [&](int buf) {
        unsigned long long p0, p1, p2, p3;
        asm("mov.b64 %0, {%1, %1};" : "=l"(p0) : "f"(aReg.x));
        asm("mov.b64 %0, {%1, %1};" : "=l"(p1) : "f"(aReg.y));
        asm("mov.b64 %0, {%1, %1};" : "=l"(p2) : "f"(aReg.z));
        asm("mov.b64 %0, {%1, %1};" : "=l"(p3) : "f"(aReg.w));
        As2[buf][akl + 0][arow] = p0;
        As2[buf][akl + 1][arow] = p1;
        As2[buf][akl + 2][arow] = p2;
        As2[buf][akl + 3][arow] = p3;
        *reinterpret_cast<float4*>(&Bs[buf][brow][bcol]) = bReg;
    };

    const int nchunks = (K + 7) / 8;
    load_regs(0);
    store_smem(0);
    __syncthreads();

    int cur = 0;
    for (int c = 0; c < nchunks; c++) {
        const bool more = (c + 1 < nchunks);
        if (more) load_regs((c + 1) * 8);

#pragma unroll
        for (int k = 0; k < 8; k++) {
            ulonglong2 u0 = *reinterpret_cast<const ulonglong2*>(&Bs[cur][k][tx * 4]);
            ulonglong2 u1 = *reinterpret_cast<const ulonglong2*>(&Bs[cur][k][64 + tx * 4]);
            unsigned long long bp[4] = {u0.x, u0.y, u1.x, u1.y};
            const ulonglong2* ap = reinterpret_cast<const ulonglong2*>(&As2[cur][k][ty * 8]);
            ulonglong2 a01 = ap[0], a23 = ap[1], a45 = ap[2], a67 = ap[3];
            unsigned long long av[8] = {a01.x, a01.y, a23.x, a23.y,
                                        a45.x, a45.y, a67.x, a67.y};
#pragma unroll
            for (int i = 0; i < 8; i++)
#pragma unroll
                for (int j = 0; j < 4; j++)
                    asm("fma.rn.f32x2 %0, %1, %2, %0;"
                        : "+l"(acc[i][j]) : "l"(av[i]), "l"(bp[j]));
        }

        if (more) store_smem(cur ^ 1);
        __syncthreads();
        cur ^= 1;
    }

    float4 bb0 = *reinterpret_cast<const float4*>(bias + tx * 4);
    float4 bb1 = *reinterpret_cast<const float4*>(bias + 64 + tx * 4);
    float bia[8] = {bb0.x, bb0.y, bb0.z, bb0.w, bb1.x, bb1.y, bb1.z, bb1.w};

#pragma unroll
    for (int i = 0; i < 8; i++) {
        int r = row0 + ty * 8 + i;
        if (r >= M) break;
        float os = out_scale ? __ldg(out_scale + r) : 1.f;
        float v[8];
#pragma unroll
        for (int j = 0; j < 4; j++) {
            float lo, hi;
            asm("mov.b64 {%0, %1}, %2;" : "=f"(lo), "=f"(hi) : "l"(acc[i][j]));
            v[2 * j]     = lo;
            v[2 * j + 1] = hi;
        }
#pragma unroll
        for (int j = 0; j < 8; j++) {
            float w = v[j] + bia[j];
            if (apply_silu) w = fast_silu(w);
            v[j] = w * os;
        }
        if (Ch) {
#pragma unroll
            for (int gblk = 0; gblk < 2; gblk++) {
                unsigned short hs[4], ls[4];
#pragma unroll
                for (int j = 0; j < 4; j++) {
                    float w = v[gblk * 4 + j];
                    __nv_bfloat16 hb = __float2bfloat16(w);
                    hs[j] = __bfloat16_as_ushort(hb);
                    ls[j] = __bfloat16_as_ushort(__float2bfloat16(w - __bfloat162float(hb)));
                }
                uint2 uh, ul;
                uh.x = (uint32_t)hs[0] | ((uint32_t)hs[1] << 16);
                uh.y = (uint32_t)hs[2] | ((uint32_t)hs[3] << 16);
                ul.x = (uint32_t)ls[0] | ((uint32_t)ls[1] << 16);
                ul.y = (uint32_t)ls[2] | ((uint32_t)ls[3] << 16);
                size_t o = (size_t)r * 128 + gblk * 64 + tx * 4;
                *reinterpret_cast<uint2*>(Ch + o) = uh;
                *reinterpret_cast<uint2*>(Cl + o) = ul;
            }
        } else {
            *reinterpret_cast<float4*>(C + (size_t)r * 128 + tx * 4) =
                make_float4(v[0], v[1], v[2], v[3]);
            *reinterpret_cast<float4*>(C + (size_t)r * 128 + 64 + tx * 4) =
                make_float4(v[4], v[5], v[6], v[7]);
        }
    }
}

// ---------------- launch ----------------
extern "C" void kernel_launch(void* const* d_in, const int* in_sizes, int n_in,
                              void* d_out, int out_size) {
    const float* x     = (const float*)d_in[0];
    const int*   src   = (const int*)  d_in[1];
    const int*   dst   = (const int*)  d_in[2];
    const int*   gid   = (const int*)  d_in[3];
    const float* w_in  = (const float*)d_in[4];
    const float* b_in  = (const float*)d_in[5];
    const float* gw    = (const float*)d_in[6];
    const float* gb    = (const float*)d_in[7];
    const float* w_out = (const float*)d_in[8];
    const float* b_out = (const float*)d_in[9];
    const float* w_ff  = (const float*)d_in[10];
    const float* b_ff  = (const float*)d_in[11];
    float* out = (float*)d_out;

    float *pooled, *nsrc;
    __nv_bfloat16 *hhi, *hlo, *ahi, *alo, *wthi, *wtlo;
    cudaGetSymbolAddress((void**)&pooled, g_pooled);
    cudaGetSymbolAddress((void**)&nsrc,   g_norm_src);
    cudaGetSymbolAddress((void**)&hhi,    g_h_hi);
    cudaGetSymbolAddress((void**)&hlo,    g_h_lo);
    cudaGetSymbolAddress((void**)&ahi,    g_agg_hi);
    cudaGetSymbolAddress((void**)&alo,    g_agg_lo);
    cudaGetSymbolAddress((void**)&wthi,   g_wt_hi);
    cudaGetSymbolAddress((void**)&wtlo,   g_wt_lo);

    cudaFuncSetAttribute(tgemm_kernel, cudaFuncAttributeMaxDynamicSharedMemorySize, TG_SMEM);

    const int rowTiles = (N_NODES + 127) / 128;  // 1563

    prep_kernel<<<(N_GRAPHS * HID / 4 + 255) / 256, 256>>>(gw, w_out);            // 1
    degree_kernel<<<(N_EDGES + 255) / 256, 256>>>(src, dst);                      // 2
    norm_kernel<<<(N_NODES + 255) / 256, 256>>>();                                // 3

    // h = silu(x @ w_in + b_in) * norm_src  -> split bf16
    gemm_kernel<<<rowTiles, 256>>>(x, N_NODES, IN_F, IN_F, w_in, b_in,            // 4
                                   nsrc, 1, nullptr, hhi, hlo);

    scan1_kernel<<<N_SCANB, SCAN_B>>>();                                          // 5
    scan2_kernel<<<1, 256>>>();                                                   // 6
    scan3_kernel<<<(N_NODES + 255) / 256, 256>>>();                               // 7
    build_csr_kernel<<<(N_EDGES + 255) / 256, 256>>>(src, dst);                   // 8

    for (int l = 0; l < 3; l++) {
        gather_kernel<<<(N_NODES * 32 + 255) / 256, 256>>>();
        tgemm_kernel<<<rowTiles, 256, TG_SMEM>>>(
            ahi, alo, wthi + (size_t)l * HID * HID, wtlo + (size_t)l * HID * HID,
            gb + (size_t)l * HID, (l < 2) ? nsrc : nullptr,
            hhi, hlo, nullptr);
    }

    // pool: pooled[gid] += silu(h @ w_out + b_out)
    tgemm_kernel<<<rowTiles, 256, TG_SMEM>>>(
        hhi, hlo, wthi + (size_t)3 * HID * HID, wtlo + (size_t)3 * HID * HID,
        b_out, nullptr, nullptr, nullptr, gid);

    // out = pooled @ w_ff + b_ff  (fp32 FFMA)
    gemm_kernel<<<(N_GRAPHS + 127) / 128, 256>>>(pooled, N_GRAPHS, HID, HID, w_ff, b_ff,
                                                 nullptr, 0, out, nullptr, nullptr);
}

// round 10
// speedup vs baseline: 2.1048x; 1.0870x over previous
#include <cuda_runtime.h>
#include <cuda_bf16.h>
#include <cstdint>

#define N_NODES  200000
#define N_EDGES  1600000
#define N_GRAPHS 10000
#define IN_F     74
#define HID      128

#define SCAN_B   1024
#define N_SCANB  ((N_NODES + SCAN_B - 1) / SCAN_B)   // 196

// interleaved split rows: h/agg = 256 bf16 [hi128|lo128] = 512B; x = 160 bf16 [hi80|lo80] = 320B
__device__ __align__(16) __nv_bfloat16 g_h  [(size_t)N_NODES * 256];
__device__ __align__(16) __nv_bfloat16 g_agg[(size_t)N_NODES * 256];
__device__ __align__(16) __nv_bfloat16 g_xs [(size_t)N_NODES * 160];
__device__ __align__(16) __nv_bfloat16 g_w  [4 * HID * 256];     // [l][n][hi128|lo128], W^T
__device__ __align__(16) __nv_bfloat16 g_win[HID * 160];         // w_in^T [n][hi80|lo80]
__device__ __align__(16) int   g_deg_out[N_NODES];
__device__ __align__(16) int   g_deg_in [N_NODES];
__device__ __align__(16) float g_norm_src[N_NODES];
__device__ __align__(16) float g_norm_dst[N_NODES];
__device__ __align__(16) float g_pooled[(size_t)N_GRAPHS * HID];
__device__ __align__(16) int   g_row_ptr[N_NODES + 1];
__device__ __align__(16) int   g_cursor [N_NODES];
__device__ __align__(16) int   g_csr_src[N_EDGES];
__device__ __align__(16) int   g_bsums  [N_SCANB];

__device__ __forceinline__ float fast_silu(float w) {
    float t, r;
    asm("ex2.approx.f32 %0, %1;" : "=f"(t) : "f"(-1.4426950408889634f * w));
    asm("rcp.approx.f32 %0, %1;" : "=f"(r) : "f"(1.f + t));
    return w * r;
}

__device__ __forceinline__ uint32_t smem_u32(const void* p) {
    uint32_t a;
    asm("{ .reg .u64 t; cvta.to.shared.u64 t, %1; cvt.u32.u64 %0, t; }" : "=r"(a) : "l"(p));
    return a;
}

#define LDSM4(r, addr)                                                          \
    asm volatile("ldmatrix.sync.aligned.m8n8.x4.shared.b16 {%0,%1,%2,%3}, [%4];" \
                 : "=r"((r)[0]), "=r"((r)[1]), "=r"((r)[2]), "=r"((r)[3])        \
                 : "r"(addr))

#define MMA16816(c, a, b)                                                        \
    asm volatile("mma.sync.aligned.m16n8k16.row.col.f32.bf16.bf16.f32 "          \
                 "{%0,%1,%2,%3}, {%4,%5,%6,%7}, {%8,%9}, {%0,%1,%2,%3};"         \
                 : "+f"((c)[0]), "+f"((c)[1]), "+f"((c)[2]), "+f"((c)[3])        \
                 : "r"((a)[0]), "r"((a)[1]), "r"((a)[2]), "r"((a)[3]),           \
                   "r"((b)[0]), "r"((b)[1]))

__device__ __forceinline__ void split_store2(float va, float vb, __nv_bfloat16* hi_p,
                                             __nv_bfloat16* lo_p) {
    __nv_bfloat16 ha = __float2bfloat16(va);
    __nv_bfloat16 hb = __float2bfloat16(vb);
    *reinterpret_cast<uint32_t*>(hi_p) =
        (uint32_t)__bfloat16_as_ushort(ha) | ((uint32_t)__bfloat16_as_ushort(hb) << 16);
    *reinterpret_cast<uint32_t*>(lo_p) =
        (uint32_t)__bfloat16_as_ushort(__float2bfloat16(va - __bfloat162float(ha)))
      | ((uint32_t)__bfloat16_as_ushort(__float2bfloat16(vb - __bfloat162float(hb))) << 16);
}

// ---------------- prep: zero counters/pooled + split/transpose all weights ----------------
__global__ void prep_kernel(const float* __restrict__ gw, const float* __restrict__ w_out,
                            const float* __restrict__ w_in) {
    int i = blockIdx.x * blockDim.x + threadIdx.x;
    if (i < N_NODES / 4) {
        reinterpret_cast<int4*>(g_deg_out)[i] = make_int4(0, 0, 0, 0);
        reinterpret_cast<int4*>(g_deg_in )[i] = make_int4(0, 0, 0, 0);
    }
    if (i < N_GRAPHS * HID / 4)
        reinterpret_cast<float4*>(g_pooled)[i] = make_float4(0.f, 0.f, 0.f, 0.f);
    if (i < 4 * HID * HID) {
        int l = i >> 14, n = (i >> 7) & 127, k = i & 127;
        float v = (l < 3) ? gw[l * HID * HID + k * HID + n] : w_out[k * HID + n];
        __nv_bfloat16 hb = __float2bfloat16(v);
        size_t base = ((size_t)(l * 128 + n)) * 256;
        g_w[base + k]       = hb;
        g_w[base + 128 + k] = __float2bfloat16(v - __bfloat162float(hb));
    }
    if (i < HID * 80) {
        int n = i / 80, k = i % 80;
        float v = (k < IN_F) ? w_in[k * HID + n] : 0.f;
        __nv_bfloat16 hb = __float2bfloat16(v);
        g_win[n * 160 + k]      = hb;
        g_win[n * 160 + 80 + k] = __float2bfloat16(v - __bfloat162float(hb));
    }
}

// split x [N,74] fp32 -> g_xs interleaved [hi80|lo80] bf16 (cols 74..79 zero). 1 warp/row.
__global__ __launch_bounds__(256) void xsplit_kernel(const float* __restrict__ x) {
    int row  = (blockIdx.x * blockDim.x + threadIdx.x) >> 5;
    int lane = threadIdx.x & 31;
    if (row >= N_NODES) return;
    const float* xr = x + (size_t)row * IN_F;
    __nv_bfloat16* o = g_xs + (size_t)row * 160;
#pragma unroll
    for (int c = lane; c < 80; c += 32) {
        float v = (c < IN_F) ? __ldg(xr + c) : 0.f;
        __nv_bfloat16 hb = __float2bfloat16(v);
        o[c]      = hb;
        o[80 + c] = __float2bfloat16(v - __bfloat162float(hb));
    }
}

__global__ void degree_kernel(const int* __restrict__ src, const int* __restrict__ dst) {
    int i = blockIdx.x * blockDim.x + threadIdx.x;
    if (i < N_EDGES) {
        atomicAdd(&g_deg_out[src[i]], 1);
        atomicAdd(&g_deg_in [dst[i]], 1);
    }
}

__global__ void norm_kernel() {
    int i = blockIdx.x * blockDim.x + threadIdx.x;
    if (i < N_NODES) {
        g_norm_src[i] = rsqrtf(fmaxf((float)g_deg_out[i], 1.f));
        g_norm_dst[i] = rsqrtf(fmaxf((float)g_deg_in [i], 1.f));
    }
}

// ---------------- CSR build ----------------
__global__ __launch_bounds__(SCAN_B) void scan1_kernel() {
    __shared__ int sh[SCAN_B];
    int i = blockIdx.x * SCAN_B + threadIdx.x;
    int v = (i < N_NODES) ? g_deg_in[i] : 0;
    sh[threadIdx.x] = v;
    __syncthreads();
#pragma unroll
    for (int off = 1; off < SCAN_B; off <<= 1) {
        int t = (threadIdx.x >= off) ? sh[threadIdx.x - off] : 0;
        __syncthreads();
        sh[threadIdx.x] += t;
        __syncthreads();
    }
    if (i < N_NODES) g_row_ptr[i] = sh[threadIdx.x] - v;
    if (threadIdx.x == SCAN_B - 1) g_bsums[blockIdx.x] = sh[threadIdx.x];
}

__global__ __launch_bounds__(256) void scan2_kernel() {
    __shared__ int sh[256];
    int v = (threadIdx.x < N_SCANB) ? g_bsums[threadIdx.x] : 0;
    sh[threadIdx.x] = v;
    __syncthreads();
#pragma unroll
    for (int off = 1; off < 256; off <<= 1) {
        int t = (threadIdx.x >= off) ? sh[threadIdx.x - off] : 0;
        __syncthreads();
        sh[threadIdx.x] += t;
        __syncthreads();
    }
    if (threadIdx.x < N_SCANB) g_bsums[threadIdx.x] = sh[threadIdx.x] - v;
}

__global__ void scan3_kernel() {
    int i = blockIdx.x * blockDim.x + threadIdx.x;
    if (i < N_NODES) {
        int rp = g_row_ptr[i] + g_bsums[i / SCAN_B];
        g_row_ptr[i] = rp;
        g_cursor [i] = rp;
    }
    if (i == 0) g_row_ptr[N_NODES] = N_EDGES;
}

__global__ void build_csr_kernel(const int* __restrict__ src, const int* __restrict__ dst) {
    int e = blockIdx.x * blockDim.x + threadIdx.x;
    if (e < N_EDGES) {
        int pos = atomicAdd(&g_cursor[dst[e]], 1);
        g_csr_src[pos] = src[e];
    }
}

// ---------------- SpMM gather: one warp/node, 1 LDG.128/lane/edge, shfl hi+lo combine ---
__global__ __launch_bounds__(256) void gather_kernel() {
    int n    = (blockIdx.x * blockDim.x + threadIdx.x) >> 5;
    int lane = threadIdx.x & 31;
    if (n >= N_NODES) return;
    int e0 = __ldg(&g_row_ptr[n]);
    int e1 = __ldg(&g_row_ptr[n + 1]);
    float acc[8];
#pragma unroll
    for (int j = 0; j < 8; j++) acc[j] = 0.f;

    int e = e0;
    for (; e + 2 <= e1; e += 2) {
        int a = __ldg(&g_csr_src[e]);
        int b = __ldg(&g_csr_src[e + 1]);
        uint4 ra = *reinterpret_cast<const uint4*>((const char*)g_h + (size_t)a * 512 + lane * 16);
        uint4 rb = *reinterpret_cast<const uint4*>((const char*)g_h + (size_t)b * 512 + lane * 16);
        const uint32_t* pa = &ra.x;
        const uint32_t* pb = &rb.x;
#pragma unroll
        for (int q = 0; q < 4; q++) {
            __nv_bfloat162 ua = *reinterpret_cast<const __nv_bfloat162*>(&pa[q]);
            __nv_bfloat162 ub = *reinterpret_cast<const __nv_bfloat162*>(&pb[q]);
            acc[2 * q]     += __bfloat162float(ua.x) + __bfloat162float(ub.x);
            acc[2 * q + 1] += __bfloat162float(ua.y) + __bfloat162float(ub.y);
        }
    }
    if (e < e1) {
        int a = __ldg(&g_csr_src[e]);
        uint4 ra = *reinterpret_cast<const uint4*>((const char*)g_h + (size_t)a * 512 + lane * 16);
        const uint32_t* pa = &ra.x;
#pragma unroll
        for (int q = 0; q < 4; q++) {
            __nv_bfloat162 ua = *reinterpret_cast<const __nv_bfloat162*>(&pa[q]);
            acc[2 * q]     += __bfloat162float(ua.x);
            acc[2 * q + 1] += __bfloat162float(ua.y);
        }
    }
    // lanes 0-15 hold hi sums of cols lane*8..+7; lanes 16-31 hold lo sums of same cols
    float nd = __ldg(&g_norm_dst[n]);
    float w[8];
#pragma unroll
    for (int j = 0; j < 8; j++) {
        float other = __shfl_down_sync(0xffffffffu, acc[j], 16);
        w[j] = (acc[j] + other) * nd;
    }
    if (lane < 16) {
        __nv_bfloat16* rowp = g_agg + (size_t)n * 256;
#pragma unroll
        for (int q = 0; q < 4; q++)
            split_store2(w[2 * q], w[2 * q + 1],
                         rowp + lane * 8 + 2 * q,
                         rowp + 128 + lane * 8 + 2 * q);
    }
}

// ---------------- HMMA GEMM (templated K): D[128,128] = (Ah+Al) @ (Wh+Wl), 3-term ------
// Rows interleaved [hi|lo], ROWB bytes; SMEM row stride TROWB (conflict-free ldmatrix).
template<int KSTEPS, int TROWB, int LOOFF, int ROWB>
__global__ __launch_bounds__(256)
void tgemm_kernel(const uint8_t* __restrict__ A8,     // rows of ROWB bytes
                  const uint8_t* __restrict__ W8,     // 128 rows of ROWB bytes (W^T split)
                  const float* __restrict__ bias,
                  const float* __restrict__ out_scale,
                  __nv_bfloat16* __restrict__ o,      // interleaved 256/row (if gids null)
                  const int* __restrict__ gids)
{
    extern __shared__ char smem[];
    const int OFF_A = 1024;
    const int OFF_W = OFF_A + 128 * TROWB;
    uint32_t sb = smem_u32(smem);
    const int tid = threadIdx.x, wid = tid >> 5, lane = tid & 31;
    const int row0 = blockIdx.x * 128;
    const int valid = min(128, N_NODES - row0);

    if (tid == 0)
        asm volatile("mbarrier.init.shared.b64 [%0], %1;" :: "r"(sb), "r"(1u) : "memory");
    if (tid < 128) ((float*)(smem + 16))[tid] = bias[tid];
    __syncthreads();

    if (tid == 0) {
        uint32_t tx = (uint32_t)(128 + valid) * ROWB;
        asm volatile("mbarrier.arrive.expect_tx.shared.b64 _, [%0], %1;"
                     :: "r"(sb), "r"(tx) : "memory");
    }
    {   // 256 row copies: tid<128 -> W row tid; tid>=128 -> A row tid-128
        int arr = tid >> 7, row = tid & 127;
        if (arr == 0) {
            asm volatile("cp.async.bulk.shared::cluster.global.mbarrier::complete_tx::bytes "
                         "[%0], [%1], %2, [%3];"
                         :: "r"(sb + OFF_W + row * TROWB), "l"(W8 + (size_t)row * ROWB),
                            "r"((uint32_t)ROWB), "r"(sb) : "memory");
        } else if (row < valid) {
            asm volatile("cp.async.bulk.shared::cluster.global.mbarrier::complete_tx::bytes "
                         "[%0], [%1], %2, [%3];"
                         :: "r"(sb + OFF_A + row * TROWB), "l"(A8 + (size_t)(row0 + row) * ROWB),
                            "r"((uint32_t)ROWB), "r"(sb) : "memory");
        }
    }
    {
        uint32_t done;
        asm volatile("{\n\t.reg .pred p;\n\t"
                     "mbarrier.try_wait.parity.acquire.cta.shared::cta.b64 p, [%1], 0;\n\t"
                     "selp.b32 %0, 1, 0, p;\n\t}" : "=r"(done) : "r"(sb) : "memory");
        if (!done) {
            asm volatile("{\n\t.reg .pred P1;\n\t"
                         "WL_%=:\n\t"
                         "mbarrier.try_wait.parity.acquire.cta.shared::cta.b64 P1, [%0], 0, 0x989680;\n\t"
                         "@P1 bra.uni WD_%=;\n\t"
                         "bra.uni WL_%=;\n\t"
                         "WD_%=:\n\t}" :: "r"(sb) : "memory");
        }
    }
    __syncthreads();

    const int wm = wid >> 1, wn = wid & 1;
    const int r0 = wm * 32, n0 = wn * 64;

    float acc[2][8][4];
#pragma unroll
    for (int m = 0; m < 2; m++)
#pragma unroll
        for (int j = 0; j < 8; j++)
#pragma unroll
            for (int q = 0; q < 4; q++) acc[m][j][q] = 0.f;

    const int arow = lane & 15;
    const int akb  = (lane >> 4) << 4;
    const int bn   = (lane & 7) + ((lane >> 4) << 3);
    const int bkb  = ((lane >> 3) & 1) << 4;

#pragma unroll
    for (int ks = 0; ks < KSTEPS; ks++) {
        uint32_t ah[2][4], al[2][4], bh[8][2], bl[8][2];
#pragma unroll
        for (int m = 0; m < 2; m++) {
            uint32_t ad = sb + OFF_A + (uint32_t)(r0 + m * 16 + arow) * TROWB + ks * 32 + akb;
            LDSM4(ah[m], ad);
            LDSM4(al[m], ad + LOOFF);
        }
#pragma unroll
        for (int jp = 0; jp < 4; jp++) {
            uint32_t bd = sb + OFF_W + (uint32_t)(n0 + jp * 16 + bn) * TROWB + ks * 32 + bkb;
            uint32_t r[4];
            LDSM4(r, bd);
            bh[2 * jp][0] = r[0]; bh[2 * jp][1] = r[1];
            bh[2 * jp + 1][0] = r[2]; bh[2 * jp + 1][1] = r[3];
            LDSM4(r, bd + LOOFF);
            bl[2 * jp][0] = r[0]; bl[2 * jp][1] = r[1];
            bl[2 * jp + 1][0] = r[2]; bl[2 * jp + 1][1] = r[3];
        }
#pragma unroll
        for (int m = 0; m < 2; m++)
#pragma unroll
            for (int j = 0; j < 8; j++) {
                MMA16816(acc[m][j], ah[m], bh[j]);
                MMA16816(acc[m][j], ah[m], bl[j]);
                MMA16816(acc[m][j], al[m], bh[j]);
            }
    }

    // ---- epilogue ----
    const float* bs = (const float*)(smem + 16);
    const int cp = n0 + (lane & 3) * 2;
#pragma unroll
    for (int m = 0; m < 2; m++) {
#pragma unroll
        for (int hf = 0; hf < 2; hf++) {
            int gr = row0 + r0 + m * 16 + hf * 8 + (lane >> 2);
            if (gr >= N_NODES) continue;
            if (gids) {
                int g = __ldg(gids + gr);
                float* pb = g_pooled + (size_t)g * 128 + cp;
#pragma unroll
                for (int j = 0; j < 8; j++) {
                    int c = cp + j * 8;
                    float va = fast_silu(acc[m][j][hf * 2 + 0] + bs[c]);
                    float vb = fast_silu(acc[m][j][hf * 2 + 1] + bs[c + 1]);
                    asm volatile("red.global.add.v2.f32 [%0], {%1,%2};"
                                 :: "l"(pb + j * 8), "f"(va), "f"(vb) : "memory");
                }
            } else {
                float os = out_scale ? __ldg(out_scale + gr) : 1.f;
                __nv_bfloat16* rowp = o + (size_t)gr * 256;
#pragma unroll
                for (int j = 0; j < 8; j++) {
                    int c = cp + j * 8;
                    float va = fast_silu(acc[m][j][hf * 2 + 0] + bs[c]) * os;
                    float vb = fast_silu(acc[m][j][hf * 2 + 1] + bs[c + 1]) * os;
                    split_store2(va, vb, rowp + c, rowp + 128 + c);
                }
            }
        }
    }
    __syncthreads();
    if (tid == 0)
        asm volatile("mbarrier.inval.shared.b64 [%0];" :: "r"(sb) : "memory");
}

// ---------------- FFMA GEMM (final w_ff only: pooled[10000,128] @ w_ff, fp32 out) -------
__global__ __launch_bounds__(256, 2)
void gemm_kernel(const float* __restrict__ A, int M,
                 const float* __restrict__ B, const float* __restrict__ bias,
                 float* __restrict__ C)
{
    __shared__ unsigned long long As2[2][8][128];
    __shared__ float              Bs [2][8][128];

    const int t    = threadIdx.x;
    const int tx   = t & 15;
    const int ty   = t >> 4;
    const int row0 = blockIdx.x * 128;

    const int arow = t >> 1;
    const int akl  = (t & 1) * 4;
    const int brow = t >> 5;
    const int bcol = (t & 31) * 4;
    const int gr   = row0 + arow;

    unsigned long long acc[8][4];
#pragma unroll
    for (int i = 0; i < 8; i++)
#pragma unroll
        for (int j = 0; j < 4; j++) acc[i][j] = 0ULL;

    float4 aReg, bReg;
    auto load_regs = [&](int k0) {
        aReg = (gr < M) ? *reinterpret_cast<const float4*>(A + (size_t)gr * 128 + k0 + akl)
                        : make_float4(0.f, 0.f, 0.f, 0.f);
        bReg = *reinterpret_cast<const float4*>(B + (size_t)(k0 + brow) * 128 + bcol);
    };
    auto store_smem = [&](int buf) {
        unsigned long long p0, p1, p2, p3;
        asm("mov.b64 %0, {%1, %1};" : "=l"(p0) : "f"(aReg.x));
        asm("mov.b64 %0, {%1, %1};" : "=l"(p1) : "f"(aReg.y));
        asm("mov.b64 %0, {%1, %1};" : "=l"(p2) : "f"(aReg.z));
        asm("mov.b64 %0, {%1, %1};" : "=l"(p3) : "f"(aReg.w));
        As2[buf][akl + 0][arow] = p0;
        As2[buf][akl + 1][arow] = p1;
        As2[buf][akl + 2][arow] = p2;
        As2[buf][akl + 3][arow] = p3;
        *reinterpret_cast<float4*>(&Bs[buf][brow][bcol]) = bReg;
    };

    load_regs(0);
    store_smem(0);
    __syncthreads();
    int cur = 0;
    for (int c = 0; c < 16; c++) {
        const bool more = (c + 1 < 16);
        if (more) load_regs((c + 1) * 8);
#pragma unroll
        for (int k = 0; k < 8; k++) {
            ulonglong2 u0 = *reinterpret_cast<const ulonglong2*>(&Bs[cur][k][tx * 4]);
            ulonglong2 u1 = *reinterpret_cast<const ulonglong2*>(&Bs[cur][k][64 + tx * 4]);
            unsigned long long bp[4] = {u0.x, u0.y, u1.x, u1.y};
            const ulonglong2* ap = reinterpret_cast<const ulonglong2*>(&As2[cur][k][ty * 8]);
            ulonglong2 a01 = ap[0], a23 = ap[1], a45 = ap[2], a67 = ap[3];
            unsigned long long av[8] = {a01.x, a01.y, a23.x, a23.y,
                                        a45.x, a45.y, a67.x, a67.y};
#pragma unroll
            for (int i = 0; i < 8; i++)
#pragma unroll
                for (int j = 0; j < 4; j++)
                    asm("fma.rn.f32x2 %0, %1, %2, %0;"
                        : "+l"(acc[i][j]) : "l"(av[i]), "l"(bp[j]));
        }
        if (more) store_smem(cur ^ 1);
        __syncthreads();
        cur ^= 1;
    }

    float4 bb0 = *reinterpret_cast<const float4*>(bias + tx * 4);
    float4 bb1 = *reinterpret_cast<const float4*>(bias + 64 + tx * 4);
    float bia[8] = {bb0.x, bb0.y, bb0.z, bb0.w, bb1.x, bb1.y, bb1.z, bb1.w};
#pragma unroll
    for (int i = 0; i < 8; i++) {
        int r = row0 + ty * 8 + i;
        if (r >= M) break;
        float v[8];
#pragma unroll
        for (int j = 0; j < 4; j++) {
            float lo, hi;
            asm("mov.b64 {%0, %1}, %2;" : "=f"(lo), "=f"(hi) : "l"(acc[i][j]));
            v[2 * j] = lo + bia[2 * j];
            v[2 * j + 1] = hi + bia[2 * j + 1];
        }
        *reinterpret_cast<float4*>(C + (size_t)r * 128 + tx * 4) =
            make_float4(v[0], v[1], v[2], v[3]);
        *reinterpret_cast<float4*>(C + (size_t)r * 128 + 64 + tx * 4) =
            make_float4(v[4], v[5], v[6], v[7]);
    }
}

// ---------------- launch ----------------
extern "C" void kernel_launch(void* const* d_in, const int* in_sizes, int n_in,
                              void* d_out, int out_size) {
    const float* x     = (const float*)d_in[0];
    const int*   src   = (const int*)  d_in[1];
    const int*   dst   = (const int*)  d_in[2];
    const int*   gid   = (const int*)  d_in[3];
    const float* w_in  = (const float*)d_in[4];
    const float* b_in  = (const float*)d_in[5];
    const float* gw    = (const float*)d_in[6];
    const float* gb    = (const float*)d_in[7];
    const float* w_out = (const float*)d_in[8];
    const float* b_out = (const float*)d_in[9];
    const float* w_ff  = (const float*)d_in[10];
    const float* b_ff  = (const float*)d_in[11];
    float* out = (float*)d_out;

    float *pooled, *nsrc;
    __nv_bfloat16 *h, *agg, *xs, *w, *win;
    cudaGetSymbolAddress((void**)&pooled, g_pooled);
    cudaGetSymbolAddress((void**)&nsrc,   g_norm_src);
    cudaGetSymbolAddress((void**)&h,      g_h);
    cudaGetSymbolAddress((void**)&agg,    g_agg);
    cudaGetSymbolAddress((void**)&xs,     g_xs);
    cudaGetSymbolAddress((void**)&w,      g_w);
    cudaGetSymbolAddress((void**)&win,    g_win);

    auto tg128 = tgemm_kernel<8, 528, 256, 512>;
    auto tg80  = tgemm_kernel<5, 336, 160, 320>;
    const int SM128 = 1024 + 2 * 128 * 528;   // 136192
    const int SM80  = 1024 + 2 * 128 * 336;   // 87040
    cudaFuncSetAttribute(tg128, cudaFuncAttributeMaxDynamicSharedMemorySize, SM128);
    cudaFuncSetAttribute(tg80,  cudaFuncAttributeMaxDynamicSharedMemorySize, SM80);

    const int rowTiles = (N_NODES + 127) / 128;  // 1563

    prep_kernel<<<(N_GRAPHS * HID / 4 + 255) / 256, 256>>>(gw, w_out, w_in);
    xsplit_kernel<<<(N_NODES * 32 + 255) / 256, 256>>>(x);
    degree_kernel<<<(N_EDGES + 255) / 256, 256>>>(src, dst);
    norm_kernel<<<(N_NODES + 255) / 256, 256>>>();

    // h = silu(xs @ w_in + b_in) * norm_src   (HMMA, K=80)
    tg80<<<rowTiles, 256, SM80>>>((const uint8_t*)xs, (const uint8_t*)win,
                                  b_in, nsrc, h, nullptr);

    scan1_kernel<<<N_SCANB, SCAN_B>>>();
    scan2_kernel<<<1, 256>>>();
    scan3_kernel<<<(N_NODES + 255) / 256, 256>>>();
    build_csr_kernel<<<(N_EDGES + 255) / 256, 256>>>(src, dst);

    for (int l = 0; l < 3; l++) {
        gather_kernel<<<(N_NODES * 32 + 255) / 256, 256>>>();
        tg128<<<rowTiles, 256, SM128>>>((const uint8_t*)agg,
                                        (const uint8_t*)(w + (size_t)l * 128 * 256),
                                        gb + (size_t)l * HID, (l < 2) ? nsrc : nullptr,
                                        h, nullptr);
    }

    // pool: pooled[gid] += silu(h @ w_out + b_out)
    tg128<<<rowTiles, 256, SM128>>>((const uint8_t*)h,
                                    (const uint8_t*)(w + (size_t)3 * 128 * 256),
                                    b_out, nullptr, nullptr, gid);

    // out = pooled @ w_ff + b_ff  (fp32 FFMA)
    gemm_kernel<<<(N_GRAPHS + 127) / 128, 256>>>(pooled, N_GRAPHS, w_ff, b_ff, out);
}

// round 12
// speedup vs baseline: 2.1445x; 1.0189x over previous
#include <cuda_runtime.h>
#include <cuda_bf16.h>
#include <cstdint>

#define N_NODES  200000
#define N_EDGES  1600000
#define N_GRAPHS 10000
#define IN_F     74
#define HID      128

#define SCAN_B   1024
#define N_SCANB  ((N_NODES + SCAN_B - 1) / SCAN_B)   // 196

// interleaved split rows: h/agg = 256 bf16 [hi128|lo128] = 512B; x = 160 bf16 [hi80|lo80] = 320B
__device__ __align__(16) __nv_bfloat16 g_h  [(size_t)N_NODES * 256];
__device__ __align__(16) __nv_bfloat16 g_agg[(size_t)N_NODES * 256];
__device__ __align__(16) __nv_bfloat16 g_xs [(size_t)N_NODES * 160];
__device__ __align__(16) __nv_bfloat16 g_w  [4 * HID * 256];     // [l][n][hi128|lo128], W^T
__device__ __align__(16) __nv_bfloat16 g_win[HID * 160];         // w_in^T [n][hi80|lo80]
__device__ __align__(16) int   g_deg_out[N_NODES];
__device__ __align__(16) int   g_deg_in [N_NODES];
__device__ __align__(16) float g_norm_src[N_NODES];
__device__ __align__(16) float g_norm_dst[N_NODES];
__device__ __align__(16) float g_pooled[(size_t)N_GRAPHS * HID];
__device__ __align__(16) int   g_row_ptr[N_NODES + 1];
__device__ __align__(16) int   g_cursor [N_NODES];
__device__ __align__(16) int   g_csr_src[N_EDGES];
__device__ __align__(16) int   g_bsums  [N_SCANB];

__device__ __forceinline__ float fast_silu(float w) {
    float t, r;
    asm("ex2.approx.f32 %0, %1;" : "=f"(t) : "f"(-1.4426950408889634f * w));
    asm("rcp.approx.f32 %0, %1;" : "=f"(r) : "f"(1.f + t));
    return w * r;
}

__device__ __forceinline__ uint32_t smem_u32(const void* p) {
    uint32_t a;
    asm("{ .reg .u64 t; cvta.to.shared.u64 t, %1; cvt.u32.u64 %0, t; }" : "=r"(a) : "l"(p));
    return a;
}

#define LDSM4(r, addr)                                                          \
    asm volatile("ldmatrix.sync.aligned.m8n8.x4.shared.b16 {%0,%1,%2,%3}, [%4];" \
                 : "=r"((r)[0]), "=r"((r)[1]), "=r"((r)[2]), "=r"((r)[3])        \
                 : "r"(addr))

#define MMA16816(c, a, b)                                                        \
    asm volatile("mma.sync.aligned.m16n8k16.row.col.f32.bf16.bf16.f32 "          \
                 "{%0,%1,%2,%3}, {%4,%5,%6,%7}, {%8,%9}, {%0,%1,%2,%3};"         \
                 : "+f"((c)[0]), "+f"((c)[1]), "+f"((c)[2]), "+f"((c)[3])        \
                 : "r"((a)[0]), "r"((a)[1]), "r"((a)[2]), "r"((a)[3]),           \
                   "r"((b)[0]), "r"((b)[1]))

__device__ __forceinline__ void split_store2(float va, float vb, __nv_bfloat16* hi_p,
                                             __nv_bfloat16* lo_p) {
    __nv_bfloat16 ha = __float2bfloat16(va);
    __nv_bfloat16 hb = __float2bfloat16(vb);
    *reinterpret_cast<uint32_t*>(hi_p) =
        (uint32_t)__bfloat16_as_ushort(ha) | ((uint32_t)__bfloat16_as_ushort(hb) << 16);
    *reinterpret_cast<uint32_t*>(lo_p) =
        (uint32_t)__bfloat16_as_ushort(__float2bfloat16(va - __bfloat162float(ha)))
      | ((uint32_t)__bfloat16_as_ushort(__float2bfloat16(vb - __bfloat162float(hb))) << 16);
}

// ---------------- fused prep: zeros + weight split/transpose + x split -----------------
__global__ __launch_bounds__(256) void prepx_kernel(const float* __restrict__ gw,
                                                    const float* __restrict__ w_out,
                                                    const float* __restrict__ w_in,
                                                    const float* __restrict__ x) {
    int i = blockIdx.x * blockDim.x + threadIdx.x;
    if (i < N_NODES / 4) {
        reinterpret_cast<int4*>(g_deg_out)[i] = make_int4(0, 0, 0, 0);
        reinterpret_cast<int4*>(g_deg_in )[i] = make_int4(0, 0, 0, 0);
    }
    if (i < N_GRAPHS * HID / 4)
        reinterpret_cast<float4*>(g_pooled)[i] = make_float4(0.f, 0.f, 0.f, 0.f);
    if (i < 4 * HID * HID) {
        int l = i >> 14, n = (i >> 7) & 127, k = i & 127;
        float v = (l < 3) ? gw[l * HID * HID + k * HID + n] : w_out[k * HID + n];
        __nv_bfloat16 hb = __float2bfloat16(v);
        size_t base = ((size_t)(l * 128 + n)) * 256;
        g_w[base + k]       = hb;
        g_w[base + 128 + k] = __float2bfloat16(v - __bfloat162float(hb));
    }
    if (i < HID * 80) {
        int n = i / 80, k = i % 80;
        float v = (k < IN_F) ? w_in[k * HID + n] : 0.f;
        __nv_bfloat16 hb = __float2bfloat16(v);
        g_win[n * 160 + k]      = hb;
        g_win[n * 160 + 80 + k] = __float2bfloat16(v - __bfloat162float(hb));
    }
    // x split: one warp per row
    int row  = i >> 5;
    int lane = i & 31;
    if (row < N_NODES) {
        const float* xr = x + (size_t)row * IN_F;
        __nv_bfloat16* o = g_xs + (size_t)row * 160;
#pragma unroll
        for (int c = lane; c < 80; c += 32) {
            float v = (c < IN_F) ? __ldg(xr + c) : 0.f;
            __nv_bfloat16 hb = __float2bfloat16(v);
            o[c]      = hb;
            o[80 + c] = __float2bfloat16(v - __bfloat162float(hb));
        }
    }
}

__global__ void degree_kernel(const int* __restrict__ src, const int* __restrict__ dst) {
    int i = blockIdx.x * blockDim.x + threadIdx.x;
    if (i < N_EDGES) {
        atomicAdd(&g_deg_out[src[i]], 1);
        atomicAdd(&g_deg_in [dst[i]], 1);
    }
}

__global__ void norm_kernel() {
    int i = blockIdx.x * blockDim.x + threadIdx.x;
    if (i < N_NODES) {
        g_norm_src[i] = rsqrtf(fmaxf((float)g_deg_out[i], 1.f));
        g_norm_dst[i] = rsqrtf(fmaxf((float)g_deg_in [i], 1.f));
    }
}

// ---------------- CSR build ----------------
__global__ __launch_bounds__(SCAN_B) void scan1_kernel() {
    __shared__ int sh[SCAN_B];
    int i = blockIdx.x * SCAN_B + threadIdx.x;
    int v = (i < N_NODES) ? g_deg_in[i] : 0;
    sh[threadIdx.x] = v;
    __syncthreads();
#pragma unroll
    for (int off = 1; off < SCAN_B; off <<= 1) {
        int t = (threadIdx.x >= off) ? sh[threadIdx.x - off] : 0;
        __syncthreads();
        sh[threadIdx.x] += t;
        __syncthreads();
    }
    if (i < N_NODES) g_row_ptr[i] = sh[threadIdx.x] - v;
    if (threadIdx.x == SCAN_B - 1) g_bsums[blockIdx.x] = sh[threadIdx.x];
}

__global__ __launch_bounds__(256) void scan2_kernel() {
    __shared__ int sh[256];
    int v = (threadIdx.x < N_SCANB) ? g_bsums[threadIdx.x] : 0;
    sh[threadIdx.x] = v;
    __syncthreads();
#pragma unroll
    for (int off = 1; off < 256; off <<= 1) {
        int t = (threadIdx.x >= off) ? sh[threadIdx.x - off] : 0;
        __syncthreads();
        sh[threadIdx.x] += t;
        __syncthreads();
    }
    if (threadIdx.x < N_SCANB) g_bsums[threadIdx.x] = sh[threadIdx.x] - v;
}

__global__ void scan3_kernel() {
    int i = blockIdx.x * blockDim.x + threadIdx.x;
    if (i < N_NODES) {
        int rp = g_row_ptr[i] + g_bsums[i / SCAN_B];
        g_row_ptr[i] = rp;
        g_cursor [i] = rp;
    }
    if (i == 0) g_row_ptr[N_NODES] = N_EDGES;
}

__global__ void build_csr_kernel(const int* __restrict__ src, const int* __restrict__ dst) {
    int e = blockIdx.x * blockDim.x + threadIdx.x;
    if (e < N_EDGES) {
        int pos = atomicAdd(&g_cursor[dst[e]], 1);
        g_csr_src[pos] = src[e];
    }
}

// ---------------- SpMM gather: one warp/node, 4 edges in flight ----------------
__global__ __launch_bounds__(256) void gather_kernel() {
    int n    = (blockIdx.x * blockDim.x + threadIdx.x) >> 5;
    int lane = threadIdx.x & 31;
    if (n >= N_NODES) return;
    int e0 = __ldg(&g_row_ptr[n]);
    int e1 = __ldg(&g_row_ptr[n + 1]);
    float acc[8];
#pragma unroll
    for (int j = 0; j < 8; j++) acc[j] = 0.f;

    int e = e0;
    for (; e + 4 <= e1; e += 4) {
        int i0 = __ldg(&g_csr_src[e]);
        int i1 = __ldg(&g_csr_src[e + 1]);
        int i2 = __ldg(&g_csr_src[e + 2]);
        int i3 = __ldg(&g_csr_src[e + 3]);
        uint4 r0 = *reinterpret_cast<const uint4*>((const char*)g_h + (size_t)i0 * 512 + lane * 16);
        uint4 r1 = *reinterpret_cast<const uint4*>((const char*)g_h + (size_t)i1 * 512 + lane * 16);
        uint4 r2 = *reinterpret_cast<const uint4*>((const char*)g_h + (size_t)i2 * 512 + lane * 16);
        uint4 r3 = *reinterpret_cast<const uint4*>((const char*)g_h + (size_t)i3 * 512 + lane * 16);
        const uint32_t* p0 = &r0.x;
        const uint32_t* p1 = &r1.x;
        const uint32_t* p2 = &r2.x;
        const uint32_t* p3 = &r3.x;
#pragma unroll
        for (int q = 0; q < 4; q++) {
            __nv_bfloat162 u0 = *reinterpret_cast<const __nv_bfloat162*>(&p0[q]);
            __nv_bfloat162 u1 = *reinterpret_cast<const __nv_bfloat162*>(&p1[q]);
            __nv_bfloat162 u2 = *reinterpret_cast<const __nv_bfloat162*>(&p2[q]);
            __nv_bfloat162 u3 = *reinterpret_cast<const __nv_bfloat162*>(&p3[q]);
            acc[2 * q]     += (__bfloat162float(u0.x) + __bfloat162float(u1.x))
                            + (__bfloat162float(u2.x) + __bfloat162float(u3.x));
            acc[2 * q + 1] += (__bfloat162float(u0.y) + __bfloat162float(u1.y))
                            + (__bfloat162float(u2.y) + __bfloat162float(u3.y));
        }
    }
    for (; e < e1; e++) {
        int a = __ldg(&g_csr_src[e]);
        uint4 ra = *reinterpret_cast<const uint4*>((const char*)g_h + (size_t)a * 512 + lane * 16);
        const uint32_t* pa = &ra.x;
#pragma unroll
        for (int q = 0; q < 4; q++) {
            __nv_bfloat162 ua = *reinterpret_cast<const __nv_bfloat162*>(&pa[q]);
            acc[2 * q]     += __bfloat162float(ua.x);
            acc[2 * q + 1] += __bfloat162float(ua.y);
        }
    }
    // lanes 0-15 hold hi sums of cols lane*8..+7; lanes 16-31 hold lo sums of same cols
    float nd = __ldg(&g_norm_dst[n]);
    float w[8];
#pragma unroll
    for (int j = 0; j < 8; j++) {
        float other = __shfl_down_sync(0xffffffffu, acc[j], 16);
        w[j] = (acc[j] + other) * nd;
    }
    if (lane < 16) {
        __nv_bfloat16* rowp = g_agg + (size_t)n * 256;
#pragma unroll
        for (int q = 0; q < 4; q++)
            split_store2(w[2 * q], w[2 * q + 1],
                         rowp + lane * 8 + 2 * q,
                         rowp + 128 + lane * 8 + 2 * q);
    }
}

// ---------------- HMMA GEMM (templated K): D[128,128] = (Ah+Al) @ (Wh+Wl), 3-term ------
template<int KSTEPS, int TROWB, int LOOFF, int ROWB>
__global__ __launch_bounds__(256)
void tgemm_kernel(const uint8_t* __restrict__ A8,
                  const uint8_t* __restrict__ W8,
                  const float* __restrict__ bias,
                  const float* __restrict__ out_scale,
                  __nv_bfloat16* __restrict__ o,
                  const int* __restrict__ gids)
{
    extern __shared__ char smem[];
    const int OFF_A = 1024;
    const int OFF_W = OFF_A + 128 * TROWB;
    uint32_t sb = smem_u32(smem);
    const int tid = threadIdx.x, wid = tid >> 5, lane = tid & 31;
    const int row0 = blockIdx.x * 128;
    const int valid = min(128, N_NODES - row0);

    if (tid == 0)
        asm volatile("mbarrier.init.shared.b64 [%0], %1;" :: "r"(sb), "r"(1u) : "memory");
    if (tid < 128) ((float*)(smem + 16))[tid] = bias[tid];
    __syncthreads();

    if (tid == 0) {
        uint32_t tx = (uint32_t)(128 + valid) * ROWB;
        asm volatile("mbarrier.arrive.expect_tx.shared.b64 _, [%0], %1;"
                     :: "r"(sb), "r"(tx) : "memory");
    }
    {
        int arr = tid >> 7, row = tid & 127;
        if (arr == 0) {
            asm volatile("cp.async.bulk.shared::cluster.global.mbarrier::complete_tx::bytes "
                         "[%0], [%1], %2, [%3];"
                         :: "r"(sb + OFF_W + row * TROWB), "l"(W8 + (size_t)row * ROWB),
                            "r"((uint32_t)ROWB), "r"(sb) : "memory");
        } else if (row < valid) {
            asm volatile("cp.async.bulk.shared::cluster.global.mbarrier::complete_tx::bytes "
                         "[%0], [%1], %2, [%3];"
                         :: "r"(sb + OFF_A + row * TROWB), "l"(A8 + (size_t)(row0 + row) * ROWB),
                            "r"((uint32_t)ROWB), "r"(sb) : "memory");
        }
    }
    {
        uint32_t done;
        asm volatile("{\n\t.reg .pred p;\n\t"
                     "mbarrier.try_wait.parity.acquire.cta.shared::cta.b64 p, [%1], 0;\n\t"
                     "selp.b32 %0, 1, 0, p;\n\t}" : "=r"(done) : "r"(sb) : "memory");
        if (!done) {
            asm volatile("{\n\t.reg .pred P1;\n\t"
                         "WL_%=:\n\t"
                         "mbarrier.try_wait.parity.acquire.cta.shared::cta.b64 P1, [%0], 0, 0x989680;\n\t"
                         "@P1 bra.uni WD_%=;\n\t"
                         "bra.uni WL_%=;\n\t"
                         "WD_%=:\n\t}" :: "r"(sb) : "memory");
        }
    }
    __syncthreads();

    const int wm = wid >> 1, wn = wid & 1;
    const int r0 = wm * 32, n0 = wn * 64;

    float acc[2][8][4];
#pragma unroll
    for (int m = 0; m < 2; m++)
#pragma unroll
        for (int j = 0; j < 8; j++)
#pragma unroll
            for (int q = 0; q < 4; q++) acc[m][j][q] = 0.f;

    const int arow = lane & 15;
    const int akb  = (lane >> 4) << 4;
    const int bn   = (lane & 7) + ((lane >> 4) << 3);
    const int bkb  = ((lane >> 3) & 1) << 4;

#pragma unroll
    for (int ks = 0; ks < KSTEPS; ks++) {
        uint32_t ah[2][4], al[2][4], bh[8][2], bl[8][2];
#pragma unroll
        for (int m = 0; m < 2; m++) {
            uint32_t ad = sb + OFF_A + (uint32_t)(r0 + m * 16 + arow) * TROWB + ks * 32 + akb;
            LDSM4(ah[m], ad);
            LDSM4(al[m], ad + LOOFF);
        }
#pragma unroll
        for (int jp = 0; jp < 4; jp++) {
            uint32_t bd = sb + OFF_W + (uint32_t)(n0 + jp * 16 + bn) * TROWB + ks * 32 + bkb;
            uint32_t r[4];
            LDSM4(r, bd);
            bh[2 * jp][0] = r[0]; bh[2 * jp][1] = r[1];
            bh[2 * jp + 1][0] = r[2]; bh[2 * jp + 1][1] = r[3];
            LDSM4(r, bd + LOOFF);
            bl[2 * jp][0] = r[0]; bl[2 * jp][1] = r[1];
            bl[2 * jp + 1][0] = r[2]; bl[2 * jp + 1][1] = r[3];
        }
#pragma unroll
        for (int m = 0; m < 2; m++)
#pragma unroll
            for (int j = 0; j < 8; j++) {
                MMA16816(acc[m][j], ah[m], bh[j]);
                MMA16816(acc[m][j], ah[m], bl[j]);
                MMA16816(acc[m][j], al[m], bh[j]);
            }
    }

    // ---- epilogue ----
    const float* bs = (const float*)(smem + 16);
    const int cp = n0 + (lane & 3) * 2;
    if (gids) {
        // run-length pre-reduction over the 4 rows this thread owns (ascending, sorted gids)
        int curg = -1;
        float p[16];
#pragma unroll
        for (int m = 0; m < 2; m++) {
#pragma unroll
            for (int hf = 0; hf < 2; hf++) {
                int gr = row0 + r0 + m * 16 + hf * 8 + (lane >> 2);
                if (gr >= N_NODES) continue;
                int g = __ldg(gids + gr);
                float v[16];
#pragma unroll
                for (int j = 0; j < 8; j++) {
                    int c = cp + j * 8;
                    v[2 * j]     = fast_silu(acc[m][j][hf * 2 + 0] + bs[c]);
                    v[2 * j + 1] = fast_silu(acc[m][j][hf * 2 + 1] + bs[c + 1]);
                }
                if (g == curg) {
#pragma unroll
                    for (int k = 0; k < 16; k++) p[k] += v[k];
                } else {
                    if (curg >= 0) {
                        float* pb = g_pooled + (size_t)curg * 128 + cp;
#pragma unroll
                        for (int j = 0; j < 8; j++)
                            asm volatile("red.global.add.v2.f32 [%0], {%1,%2};"
                                         :: "l"(pb + j * 8), "f"(p[2 * j]), "f"(p[2 * j + 1])
                                         : "memory");
                    }
                    curg = g;
#pragma unroll
                    for (int k = 0; k < 16; k++) p[k] = v[k];
                }
            }
        }
        if (curg >= 0) {
            float* pb = g_pooled + (size_t)curg * 128 + cp;
#pragma unroll
            for (int j = 0; j < 8; j++)
                asm volatile("red.global.add.v2.f32 [%0], {%1,%2};"
                             :: "l"(pb + j * 8), "f"(p[2 * j]), "f"(p[2 * j + 1])
                             : "memory");
        }
    } else {
#pragma unroll
        for (int m = 0; m < 2; m++) {
#pragma unroll
            for (int hf = 0; hf < 2; hf++) {
                int gr = row0 + r0 + m * 16 + hf * 8 + (lane >> 2);
                if (gr >= N_NODES) continue;
                float os = out_scale ? __ldg(out_scale + gr) : 1.f;
                __nv_bfloat16* rowp = o + (size_t)gr * 256;
#pragma unroll
                for (int j = 0; j < 8; j++) {
                    int c = cp + j * 8;
                    float va = fast_silu(acc[m][j][hf * 2 + 0] + bs[c]) * os;
                    float vb = fast_silu(acc[m][j][hf * 2 + 1] + bs[c + 1]) * os;
                    split_store2(va, vb, rowp + c, rowp + 128 + c);
                }
            }
        }
    }
    __syncthreads();
    if (tid == 0)
        asm volatile("mbarrier.inval.shared.b64 [%0];" :: "r"(sb) : "memory");
}

// ---------------- FFMA GEMM (final w_ff only) ----------------
__global__ __launch_bounds__(256, 2)
void gemm_kernel(const float* __restrict__ A, int M,
                 const float* __restrict__ B, const float* __restrict__ bias,
                 float* __restrict__ C)
{
    __shared__ unsigned long long As2[2][8][128];
    __shared__ float              Bs [2][8][128];

    const int t    = threadIdx.x;
    const int tx   = t & 15;
    const int ty   = t >> 4;
    const int row0 = blockIdx.x * 128;

    const int arow = t >> 1;
    const int akl  = (t & 1) * 4;
    const int brow = t >> 5;
    const int bcol = (t & 31) * 4;
    const int gr   = row0 + arow;

    unsigned long long acc[8][4];
#pragma unroll
    for (int i = 0; i < 8; i++)
#pragma unroll
        for (int j = 0; j < 4; j++) acc[i][j] = 0ULL;

    float4 aReg, bReg;
    auto load_regs = [&](int k0) {
        aReg = (gr < M) ? *reinterpret_cast<const float4*>(A + (size_t)gr * 128 + k0 + akl)
                        : make_float4(0.f, 0.f, 0.f, 0.f);
        bReg = *reinterpret_cast<const float4*>(B + (size_t)(k0 + brow) * 128 + bcol);
    };
    auto store_smem = [&](int buf) {
        unsigned long long p0, p1, p2, p3;
        asm("mov.b64 %0, {%1, %1};" : "=l"(p0) : "f"(aReg.x));
        asm("mov.b64 %0, {%1, %1};" : "=l"(p1) : "f"(aReg.y));
        asm("mov.b64 %0, {%1, %1};" : "=l"(p2) : "f"(aReg.z));
        asm("mov.b64 %0, {%1, %1};" : "=l"(p3) : "f"(aReg.w));
        As2[buf][akl + 0][arow] = p0;
        As2[buf][akl + 1][arow] = p1;
        As2[buf][akl + 2][arow] = p2;
        As2[buf][akl + 3][arow] = p3;
        *reinterpret_cast<float4*>(&Bs[buf][brow][bcol]) = bReg;
    };

    load_regs(0);
    store_smem(0);
    __syncthreads();
    int cur = 0;
    for (int c = 0; c < 16; c++) {
        const bool more = (c + 1 < 16);
        if (more) load_regs((c + 1) * 8);
#pragma unroll
        for (int k = 0; k < 8; k++) {
            ulonglong2 u0 = *reinterpret_cast<const ulonglong2*>(&Bs[cur][k][tx * 4]);
            ulonglong2 u1 = *reinterpret_cast<const ulonglong2*>(&Bs[cur][k][64 + tx * 4]);
            unsigned long long bp[4] = {u0.x, u0.y, u1.x, u1.y};
            const ulonglong2* ap = reinterpret_cast<const ulonglong2*>(&As2[cur][k][ty * 8]);
            ulonglong2 a01 = ap[0], a23 = ap[1], a45 = ap[2], a67 = ap[3];
            unsigned long long av[8] = {a01.x, a01.y, a23.x, a23.y,
                                        a45.x, a45.y, a67.x, a67.y};
#pragma unroll
            for (int i = 0; i < 8; i++)
#pragma unroll
                for (int j = 0; j < 4; j++)
                    asm("fma.rn.f32x2 %0, %1, %2, %0;"
                        : "+l"(acc[i][j]) : "l"(av[i]), "l"(bp[j]));
        }
        if (more) store_smem(cur ^ 1);
        __syncthreads();
        cur ^= 1;
    }

    float4 bb0 = *reinterpret_cast<const float4*>(bias + tx * 4);
    float4 bb1 = *reinterpret_cast<const float4*>(bias + 64 + tx * 4);
    float bia[8] = {bb0.x, bb0.y, bb0.z, bb0.w, bb1.x, bb1.y, bb1.z, bb1.w};
#pragma unroll
    for (int i = 0; i < 8; i++) {
        int r = row0 + ty * 8 + i;
        if (r >= M) break;
        float v[8];
#pragma unroll
        for (int j = 0; j < 4; j++) {
            float lo, hi;
            asm("mov.b64 {%0, %1}, %2;" : "=f"(lo), "=f"(hi) : "l"(acc[i][j]));
            v[2 * j] = lo + bia[2 * j];
            v[2 * j + 1] = hi + bia[2 * j + 1];
        }
        *reinterpret_cast<float4*>(C + (size_t)r * 128 + tx * 4) =
            make_float4(v[0], v[1], v[2], v[3]);
        *reinterpret_cast<float4*>(C + (size_t)r * 128 + 64 + tx * 4) =
            make_float4(v[4], v[5], v[6], v[7]);
    }
}

// ---------------- launch ----------------
extern "C" void kernel_launch(void* const* d_in, const int* in_sizes, int n_in,
                              void* d_out, int out_size) {
    const float* x     = (const float*)d_in[0];
    const int*   src   = (const int*)  d_in[1];
    const int*   dst   = (const int*)  d_in[2];
    const int*   gid   = (const int*)  d_in[3];
    const float* w_in  = (const float*)d_in[4];
    const float* b_in  = (const float*)d_in[5];
    const float* gw    = (const float*)d_in[6];
    const float* gb    = (const float*)d_in[7];
    const float* w_out = (const float*)d_in[8];
    const float* b_out = (const float*)d_in[9];
    const float* w_ff  = (const float*)d_in[10];
    const float* b_ff  = (const float*)d_in[11];
    float* out = (float*)d_out;

    float *pooled, *nsrc;
    __nv_bfloat16 *h, *agg, *xs, *w, *win;
    cudaGetSymbolAddress((void**)&pooled, g_pooled);
    cudaGetSymbolAddress((void**)&nsrc,   g_norm_src);
    cudaGetSymbolAddress((void**)&h,      g_h);
    cudaGetSymbolAddress((void**)&agg,    g_agg);
    cudaGetSymbolAddress((void**)&xs,     g_xs);
    cudaGetSymbolAddress((void**)&w,      g_w);
    cudaGetSymbolAddress((void**)&win,    g_win);

    auto tg128 = tgemm_kernel<8, 528, 256, 512>;
    auto tg80  = tgemm_kernel<5, 336, 160, 320>;
    const int SM128 = 1024 + 2 * 128 * 528;   // 136192
    const int SM80  = 1024 + 2 * 128 * 336;   // 87040
    cudaFuncSetAttribute(tg128, cudaFuncAttributeMaxDynamicSharedMemorySize, SM128);
    cudaFuncSetAttribute(tg80,  cudaFuncAttributeMaxDynamicSharedMemorySize, SM80);

    const int rowTiles = (N_NODES + 127) / 128;  // 1563

    // fused prep+xsplit (1), degree (2), norm (3), tg80 (4) <- profiled launch
    prepx_kernel<<<(N_NODES * 32 + 255) / 256, 256>>>(gw, w_out, w_in, x);
    degree_kernel<<<(N_EDGES + 255) / 256, 256>>>(src, dst);
    norm_kernel<<<(N_NODES + 255) / 256, 256>>>();

    // h = silu(xs @ w_in + b_in) * norm_src   (HMMA, K=80)
    tg80<<<rowTiles, 256, SM80>>>((const uint8_t*)xs, (const uint8_t*)win,
                                  b_in, nsrc, h, nullptr);

    scan1_kernel<<<N_SCANB, SCAN_B>>>();
    scan2_kernel<<<1, 256>>>();
    scan3_kernel<<<(N_NODES + 255) / 256, 256>>>();
    build_csr_kernel<<<(N_EDGES + 255) / 256, 256>>>(src, dst);

    for (int l = 0; l < 3; l++) {
        gather_kernel<<<(N_NODES * 32 + 255) / 256, 256>>>();
        tg128<<<rowTiles, 256, SM128>>>((const uint8_t*)agg,
                                        (const uint8_t*)(w + (size_t)l * 128 * 256),
                                        gb + (size_t)l * HID, (l < 2) ? nsrc : nullptr,
                                        h, nullptr);
    }

    // pool: pooled[gid] += silu(h @ w_out + b_out)
    tg128<<<rowTiles, 256, SM128>>>((const uint8_t*)h,
                                    (const uint8_t*)(w + (size_t)3 * 128 * 256),
                                    b_out, nullptr, nullptr, gid);

    // out = pooled @ w_ff + b_ff  (fp32 FFMA)
    gemm_kernel<<<(N_GRAPHS + 127) / 128, 256>>>(pooled, N_GRAPHS, w_ff, b_ff, out);
}